// round 1
// baseline (speedup 1.0000x reference)
#include <cuda_runtime.h>

// Problem constants
constexpr int NB = 8;          // batch
constexpr int NC = 256;        // embed channels
constexpr int NH = 96;
constexpr int NW = 96;
constexpr int NP = NH * NW;    // 9216 pixels
constexpr int NK = 576;        // pooled 24*24
constexpr int NHP = 24;

// ---------------- device scratch (no allocations allowed) ----------------
__device__ float g_fi[NB * NC * NK];     // pooled init_embed  (b,c,k)
__device__ float g_si[NB * 2 * NK];      // pooled init_seg    (b,2,k)
__device__ float g_aux[NB * 8 * NP];     // concat channels 256..263: [gmap0,gmap1,iseg0,iseg1,lmap0,lmap1,pseg0,pseg1]
__device__ float g_h[NB * 128 * NP];     // conv1 activations

// =========================================================================
// Kernel 1: avg_pool4 of init_embed -> g_fi, init_seg -> g_si,
//           plus copies of init_seg / prev_seg into aux channels.
// =========================================================================
__global__ void pool_kernel(const float* __restrict__ init_embed,
                            const float* __restrict__ init_seg,
                            const float* __restrict__ prev_seg) {
    int idx = blockIdx.x * blockDim.x + threadIdx.x;
    const int NFI = NB * NC * NK;
    const int NSI = NB * 2 * NK;
    const int NCP = NB * 2 * NP;
    if (idx < NFI) {
        int b = idx / (NC * NK);
        int r = idx % (NC * NK);
        int c = r / NK;
        int k = r % NK;
        int hp = k / NHP, wp = k % NHP;
        const float* src = init_embed + ((size_t)(b * NC + c) * NH + hp * 4) * NW + wp * 4;
        float s = 0.f;
        #pragma unroll
        for (int i = 0; i < 4; i++)
            #pragma unroll
            for (int j = 0; j < 4; j++) s += src[i * NW + j];
        g_fi[idx] = s * (1.f / 16.f);
    } else if (idx < NFI + NSI) {
        int t = idx - NFI;
        int b = t / (2 * NK);
        int r = t % (2 * NK);
        int c = r / NK;
        int k = r % NK;
        int hp = k / NHP, wp = k % NHP;
        const float* src = init_seg + ((size_t)(b * 2 + c) * NH + hp * 4) * NW + wp * 4;
        float s = 0.f;
        #pragma unroll
        for (int i = 0; i < 4; i++)
            #pragma unroll
            for (int j = 0; j < 4; j++) s += src[i * NW + j];
        g_si[t] = s * (1.f / 16.f);
    } else if (idx < NFI + NSI + 2 * NCP) {
        int t = idx - NFI - NSI;
        int which = t / NCP;            // 0: init_seg -> aux[2,3]; 1: prev_seg -> aux[6,7]
        int r = t % NCP;
        int b = r / (2 * NP);
        int rem = r % (2 * NP);
        int c = rem / NP;
        int p = rem % NP;
        float v = which ? prev_seg[r] : init_seg[r];
        g_aux[((size_t)b * 8 + (which ? 6 : 2) + c) * NP + p] = v;
    }
}

// =========================================================================
// Kernel 2: global map.  Per batch GEMM  sim[k,p] = sum_c fi[c,k]*cur[c,p]
// with epilogue gmap[cls,p] = max_k sim[k,p]*si[cls,k].
// Block: 64 pixels x 64 k, loops all 9 k-tiles keeping a running per-pixel max.
// =========================================================================
__global__ void gmap_kernel(const float* __restrict__ cur_embed) {
    __shared__ float sA[16][66];   // (channel, pixel)
    __shared__ float sB[16][66];   // (channel, k)
    int b = blockIdx.y;
    int p0 = blockIdx.x * 64;
    int tid = threadIdx.x;
    int tix = tid & 15;            // k group
    int tiy = tid >> 4;            // pixel group
    float m0[4], m1[4];
    #pragma unroll
    for (int ii = 0; ii < 4; ii++) { m0[ii] = -1e30f; m1[ii] = -1e30f; }

    for (int kt = 0; kt < 9; kt++) {
        int k0 = kt * 64;
        float acc[4][4] = {};
        float s0v[4], s1v[4];
        #pragma unroll
        for (int jj = 0; jj < 4; jj++) {
            int k = k0 + tix + 16 * jj;
            s0v[jj] = g_si[(b * 2 + 0) * NK + k];
            s1v[jj] = g_si[(b * 2 + 1) * NK + k];
        }
        for (int ct = 0; ct < 16; ct++) {
            int c0 = ct * 16;
            __syncthreads();
            for (int i = tid; i < 16 * 64; i += 256) {
                int cc = i >> 6, x = i & 63;
                sA[cc][x] = cur_embed[((size_t)(b * NC + c0 + cc)) * NP + p0 + x];
                sB[cc][x] = g_fi[((size_t)(b * NC + c0 + cc)) * NK + k0 + x];
            }
            __syncthreads();
            #pragma unroll
            for (int cc = 0; cc < 16; cc++) {
                float a[4], bb[4];
                #pragma unroll
                for (int ii = 0; ii < 4; ii++) a[ii] = sA[cc][tiy + 16 * ii];
                #pragma unroll
                for (int jj = 0; jj < 4; jj++) bb[jj] = sB[cc][tix + 16 * jj];
                #pragma unroll
                for (int ii = 0; ii < 4; ii++)
                    #pragma unroll
                    for (int jj = 0; jj < 4; jj++)
                        acc[ii][jj] += a[ii] * bb[jj];
            }
        }
        #pragma unroll
        for (int ii = 0; ii < 4; ii++)
            #pragma unroll
            for (int jj = 0; jj < 4; jj++) {
                m0[ii] = fmaxf(m0[ii], acc[ii][jj] * s0v[jj]);
                m1[ii] = fmaxf(m1[ii], acc[ii][jj] * s1v[jj]);
            }
    }

    // reduce max across the 16 k-groups (tix) for each pixel, per class
    float* red = &sA[0][0];   // 16*66 floats, stride 66 avoids bank conflicts
    __syncthreads();
    #pragma unroll
    for (int ii = 0; ii < 4; ii++) red[tix * 66 + tiy + 16 * ii] = m0[ii];
    __syncthreads();
    for (int s = 8; s > 0; s >>= 1) {
        if (tix < s)
            #pragma unroll
            for (int ii = 0; ii < 4; ii++) {
                int px = tiy + 16 * ii;
                red[tix * 66 + px] = fmaxf(red[tix * 66 + px], red[(tix + s) * 66 + px]);
            }
        __syncthreads();
    }
    if (tix == 0)
        #pragma unroll
        for (int ii = 0; ii < 4; ii++)
            g_aux[((size_t)b * 8 + 0) * NP + p0 + tiy + 16 * ii] = red[tiy + 16 * ii];
    __syncthreads();
    #pragma unroll
    for (int ii = 0; ii < 4; ii++) red[tix * 66 + tiy + 16 * ii] = m1[ii];
    __syncthreads();
    for (int s = 8; s > 0; s >>= 1) {
        if (tix < s)
            #pragma unroll
            for (int ii = 0; ii < 4; ii++) {
                int px = tiy + 16 * ii;
                red[tix * 66 + px] = fmaxf(red[tix * 66 + px], red[(tix + s) * 66 + px]);
            }
        __syncthreads();
    }
    if (tix == 0)
        #pragma unroll
        for (int ii = 0; ii < 4; ii++)
            g_aux[((size_t)b * 8 + 1) * NP + p0 + tiy + 16 * ii] = red[tiy + 16 * ii];
}

// =========================================================================
// Kernel 3: local correlation.  raw(p,d) = sum_c cur[c,p]*prev[c,p+d] / C
// lmap[cls,p] = max_d raw(p,d) * prev_seg[cls, p+d]   (mask factors out of the
// channel sum since seg is channel-independent; OOB displacement contributes 0).
// Tile: 4x32 pixels, 3 dy-groups x 9 dx = 27 accumulators per thread.
// =========================================================================
__global__ void corr_kernel(const float* __restrict__ cur_embed,
                            const float* __restrict__ prev_embed,
                            const float* __restrict__ prev_seg) {
    __shared__ float prevT[8][6][40];
    int b = blockIdx.z;
    int h0 = blockIdx.y * 4;
    int w0 = blockIdx.x * 32;
    int tid = threadIdx.x;         // 128 threads
    int ty = tid >> 5, tx = tid & 31;
    int hh0 = h0 + ty, ww0 = w0 + tx;
    int p = hh0 * NW + ww0;
    float m0 = -1e30f, m1 = -1e30f;

    for (int g = 0; g < 3; g++) {
        float acc[3][9];
        #pragma unroll
        for (int r = 0; r < 3; r++)
            #pragma unroll
            for (int d = 0; d < 9; d++) acc[r][d] = 0.f;
        int hbase = h0 + g * 3 - 4;
        for (int c0 = 0; c0 < NC; c0 += 8) {
            __syncthreads();
            for (int i = tid; i < 8 * 240; i += 128) {
                int cc = i / 240, rem = i % 240, rr = rem / 40, col = rem % 40;
                int hh = hbase + rr, ww = w0 - 4 + col;
                float v = 0.f;
                if (hh >= 0 && hh < NH && ww >= 0 && ww < NW)
                    v = prev_embed[((size_t)(b * NC + c0 + cc)) * NP + hh * NW + ww];
                prevT[cc][rr][col] = v;
            }
            float cv8[8];
            #pragma unroll
            for (int cc = 0; cc < 8; cc++)
                cv8[cc] = cur_embed[((size_t)(b * NC + c0 + cc)) * NP + p];
            __syncthreads();
            #pragma unroll
            for (int cc = 0; cc < 8; cc++) {
                float cv = cv8[cc];
                #pragma unroll
                for (int r = 0; r < 3; r++)
                    #pragma unroll
                    for (int d = 0; d < 9; d++)
                        acc[r][d] += cv * prevT[cc][ty + r][tx + d];
            }
        }
        #pragma unroll
        for (int r = 0; r < 3; r++) {
            int dy = g * 3 + r - 4;
            int sh = hh0 + dy;
            #pragma unroll
            for (int d = 0; d < 9; d++) {
                int sw = ww0 + d - 4;
                if (sh >= 0 && sh < NH && sw >= 0 && sw < NW) {
                    float raw = acc[r][d] * (1.f / 256.f);
                    float s0 = prev_seg[((size_t)(b * 2 + 0)) * NP + sh * NW + sw];
                    float s1 = prev_seg[((size_t)(b * 2 + 1)) * NP + sh * NW + sw];
                    m0 = fmaxf(m0, raw * s0);
                    m1 = fmaxf(m1, raw * s1);
                } else {
                    m0 = fmaxf(m0, 0.f);   // zero-padded masked feats -> corr = 0
                    m1 = fmaxf(m1, 0.f);
                }
            }
        }
    }
    g_aux[((size_t)b * 8 + 4) * NP + p] = m0;
    g_aux[((size_t)b * 8 + 5) * NP + p] = m1;
}

// =========================================================================
// Kernel 4: conv1 264->128, 3x3, SAME, ReLU.  Implicit GEMM.
// Block: 64 pixels (4x16) x 128 oc, 256 threads, 4x8 micro-tile, ic chunks of 8.
// Channels 0..255 come from cur_decode, 256..263 from g_aux (never concatenated).
// =========================================================================
__global__ void conv1_kernel(const float* __restrict__ cur_decode,
                             const float* __restrict__ W1,
                             const float* __restrict__ b1) {
    __shared__ float inT[8][6][18];
    __shared__ float wT[8 * 9 * 128];
    int b = blockIdx.z;
    int row0 = blockIdx.y * 4;
    int col0 = blockIdx.x * 16;
    int tid = threadIdx.x;
    int tix = tid & 15;    // oc group
    int tiy = tid >> 4;    // pixel column within tile
    float acc[4][8] = {};

    for (int ic0 = 0; ic0 < 264; ic0 += 8) {
        __syncthreads();
        for (int i = tid; i < 8 * 108; i += 256) {
            int ic = i / 108, rem = i % 108, r = rem / 18, c2 = rem % 18;
            int hh = row0 + r - 1, ww = col0 + c2 - 1;
            float v = 0.f;
            if (hh >= 0 && hh < NH && ww >= 0 && ww < NW) {
                int icg = ic0 + ic;
                v = (icg < 256)
                        ? cur_decode[((size_t)(b * 256 + icg)) * NP + hh * NW + ww]
                        : g_aux[((size_t)b * 8 + icg - 256) * NP + hh * NW + ww];
            }
            inT[ic][r][c2] = v;
        }
        for (int j = tid; j < 128 * 72; j += 256) {
            int oc = j / 72, rem = j % 72, ic = rem / 9, k = rem % 9;
            wT[(ic * 9 + k) * 128 + oc] = W1[(size_t)oc * 2376 + (ic0 + ic) * 9 + k];
        }
        __syncthreads();
        #pragma unroll
        for (int ic = 0; ic < 8; ic++) {
            #pragma unroll
            for (int ky = 0; ky < 3; ky++) {
                #pragma unroll
                for (int kx = 0; kx < 3; kx++) {
                    float a[4];
                    #pragma unroll
                    for (int ii = 0; ii < 4; ii++) a[ii] = inT[ic][ii + ky][tiy + kx];
                    const float* wrow = &wT[(ic * 9 + ky * 3 + kx) * 128];
                    #pragma unroll
                    for (int o = 0; o < 8; o++) {
                        float w = wrow[tix + 16 * o];
                        #pragma unroll
                        for (int ii = 0; ii < 4; ii++) acc[ii][o] += a[ii] * w;
                    }
                }
            }
        }
    }
    #pragma unroll
    for (int o = 0; o < 8; o++) {
        int oc = tix + 16 * o;
        float bias = b1[oc];
        #pragma unroll
        for (int ii = 0; ii < 4; ii++) {
            float v = acc[ii][o] + bias;
            g_h[((size_t)(b * 128 + oc)) * NP + (row0 + ii) * NW + col0 + tiy] =
                fmaxf(v, 0.f);
        }
    }
}

// =========================================================================
// Kernel 5: conv2 128->2, 3x3, SAME.  Tile 8x32 pixels, smem input halo tiles.
// =========================================================================
__global__ void conv2_kernel(const float* __restrict__ W2,
                             const float* __restrict__ b2,
                             float* __restrict__ out) {
    __shared__ float w2s[2 * 128 * 9];
    __shared__ float hT[8][10][34];
    int b = blockIdx.z;
    int row0 = blockIdx.y * 8;
    int col0 = blockIdx.x * 32;
    int tid = threadIdx.x;
    int ty = tid >> 5, tx = tid & 31;
    for (int i = tid; i < 2304; i += 256) w2s[i] = W2[i];
    float a0 = b2[0], a1 = b2[1];

    for (int ic0 = 0; ic0 < 128; ic0 += 8) {
        __syncthreads();
        for (int i = tid; i < 8 * 340; i += 256) {
            int ic = i / 340, rem = i % 340, r = rem / 34, c2 = rem % 34;
            int hh = row0 + r - 1, ww = col0 + c2 - 1;
            float v = 0.f;
            if (hh >= 0 && hh < NH && ww >= 0 && ww < NW)
                v = g_h[((size_t)(b * 128 + ic0 + ic)) * NP + hh * NW + ww];
            hT[ic][r][c2] = v;
        }
        __syncthreads();
        #pragma unroll
        for (int ic = 0; ic < 8; ic++) {
            #pragma unroll
            for (int ky = 0; ky < 3; ky++)
                #pragma unroll
                for (int kx = 0; kx < 3; kx++) {
                    float v = hT[ic][ty + ky][tx + kx];
                    int wi = (ic0 + ic) * 9 + ky * 3 + kx;
                    a0 += v * w2s[wi];
                    a1 += v * w2s[1152 + wi];
                }
        }
    }
    int p = (row0 + ty) * NW + col0 + tx;
    out[((size_t)(b * 2 + 0)) * NP + p] = a0;
    out[((size_t)(b * 2 + 1)) * NP + p] = a1;
}

// =========================================================================
extern "C" void kernel_launch(void* const* d_in, const int* in_sizes, int n_in,
                              void* d_out, int out_size) {
    const float* cur_embed  = (const float*)d_in[0];
    const float* cur_decode = (const float*)d_in[1];
    const float* init_embed = (const float*)d_in[2];
    const float* init_seg   = (const float*)d_in[3];
    const float* prev_embed = (const float*)d_in[4];
    const float* prev_seg   = (const float*)d_in[5];
    const float* W1 = (const float*)d_in[6];
    const float* b1 = (const float*)d_in[7];
    const float* W2 = (const float*)d_in[8];
    const float* b2 = (const float*)d_in[9];
    float* out = (float*)d_out;

    int npool = NB * NC * NK + NB * 2 * NK + 2 * NB * 2 * NP;
    pool_kernel<<<(npool + 255) / 256, 256>>>(init_embed, init_seg, prev_seg);
    gmap_kernel<<<dim3(NP / 64, NB), 256>>>(cur_embed);
    corr_kernel<<<dim3(NW / 32, NH / 4, NB), 128>>>(cur_embed, prev_embed, prev_seg);
    conv1_kernel<<<dim3(NW / 16, NH / 4, NB), 256>>>(cur_decode, W1, b1);
    conv2_kernel<<<dim3(NW / 32, NH / 8, NB), 256>>>(W2, b2, out);
}

// round 3
// speedup vs baseline: 1.4245x; 1.4245x over previous
#include <cuda_runtime.h>

// Problem constants
constexpr int NB = 8;          // batch
constexpr int NC = 256;        // embed channels
constexpr int NH = 96;
constexpr int NW = 96;
constexpr int NP = NH * NW;    // 9216 pixels
constexpr int NK = 576;        // pooled 24*24
constexpr int NHP = 24;

// ---------------- device scratch (no allocations allowed) ----------------
__device__ float g_fi[NB * NC * NK];     // pooled init_embed  (b,c,k)
__device__ float g_si[NB * 2 * NK];      // pooled init_seg    (b,2,k)
__device__ float g_aux[NB * 8 * NP];     // concat ch 256..263: [gmap0,gmap1,iseg0,iseg1,lmap0,lmap1,pseg0,pseg1]
__device__ float g_h[NB * 128 * NP];     // conv1 activations
__device__ float g_w1t[2376 * 128];      // W1 transposed: [(ic*9+k)][oc]

// ---------------- packed f32x2 helpers (Blackwell FFMA2) ----------------
__device__ __forceinline__ unsigned long long pk2(float lo, float hi) {
    unsigned long long r;
    asm("mov.b64 %0,{%1,%2};" : "=l"(r) : "f"(lo), "f"(hi));
    return r;
}
__device__ __forceinline__ unsigned long long f2fma(unsigned long long a,
                                                    unsigned long long b,
                                                    unsigned long long c) {
    unsigned long long d;
    asm("fma.rn.f32x2 %0,%1,%2,%3;" : "=l"(d) : "l"(a), "l"(b), "l"(c));
    return d;
}
__device__ __forceinline__ void upk2(unsigned long long p, float& lo, float& hi) {
    asm("mov.b64 {%0,%1},%2;" : "=f"(lo), "=f"(hi) : "l"(p));
}

// =========================================================================
// Kernel 1: avg_pool4 (init_embed -> g_fi, init_seg -> g_si), seg copies
// into aux channels, and one-time W1 transpose into g_w1t.
// =========================================================================
__global__ void pool_kernel(const float* __restrict__ init_embed,
                            const float* __restrict__ init_seg,
                            const float* __restrict__ prev_seg,
                            const float* __restrict__ W1) {
    int idx = blockIdx.x * blockDim.x + threadIdx.x;
    const int NFI = NB * NC * NK;
    const int NSI = NB * 2 * NK;
    const int NCP = NB * 2 * NP;
    const int NWT = 2376 * 128;
    if (idx < NFI) {
        int b = idx / (NC * NK);
        int r = idx % (NC * NK);
        int c = r / NK;
        int k = r % NK;
        int hp = k / NHP, wp = k % NHP;
        const float* src = init_embed + ((size_t)(b * NC + c) * NH + hp * 4) * NW + wp * 4;
        float s = 0.f;
        #pragma unroll
        for (int i = 0; i < 4; i++)
            #pragma unroll
            for (int j = 0; j < 4; j++) s += src[i * NW + j];
        g_fi[idx] = s * (1.f / 16.f);
    } else if (idx < NFI + NSI) {
        int t = idx - NFI;
        int b = t / (2 * NK);
        int r = t % (2 * NK);
        int c = r / NK;
        int k = r % NK;
        int hp = k / NHP, wp = k % NHP;
        const float* src = init_seg + ((size_t)(b * 2 + c) * NH + hp * 4) * NW + wp * 4;
        float s = 0.f;
        #pragma unroll
        for (int i = 0; i < 4; i++)
            #pragma unroll
            for (int j = 0; j < 4; j++) s += src[i * NW + j];
        g_si[t] = s * (1.f / 16.f);
    } else if (idx < NFI + NSI + 2 * NCP) {
        int t = idx - NFI - NSI;
        int which = t / NCP;            // 0: init_seg -> aux[2,3]; 1: prev_seg -> aux[6,7]
        int r = t % NCP;
        int b = r / (2 * NP);
        int rem = r % (2 * NP);
        int c = rem / NP;
        int p = rem % NP;
        float v = which ? prev_seg[r] : init_seg[r];
        g_aux[((size_t)b * 8 + (which ? 6 : 2) + c) * NP + p] = v;
    } else if (idx < NFI + NSI + 2 * NCP + NWT) {
        int t = idx - NFI - NSI - 2 * NCP;   // t = r*128 + oc  (coalesced writes)
        int r = t >> 7;
        int oc = t & 127;
        g_w1t[t] = W1[(size_t)oc * 2376 + r];
    }
}

// =========================================================================
// Kernel 2: global map.  sim[k,p] = sum_c fi[c,k]*cur[c,p] ;
// gmap[cls,p] = max_k sim[k,p]*si[cls,k].
// Block: 128 px x 64 k, 256 threads (32 px-thr x 8 k-thr), thread 4px x 8k.
// f32x2 pairs along k (free from LDS.128 of sB).
// =========================================================================
__global__ __launch_bounds__(256, 2) void gmap_kernel(const float* __restrict__ cur_embed) {
    __shared__ float sA[8][128];
    __shared__ float sB[8][64];
    int b = blockIdx.y;
    int p0 = blockIdx.x * 128;
    int tid = threadIdx.x;
    int ktid = tid & 7;        // 8 k-threads, each 8 k
    int ptid = tid >> 3;       // 32 px-threads, each 4 px
    float m0[4], m1[4];
    #pragma unroll
    for (int i = 0; i < 4; i++) { m0[i] = -1e30f; m1[i] = -1e30f; }

    for (int kt = 0; kt < 9; kt++) {
        int k0 = kt * 64;
        unsigned long long acc2[4][4];
        #pragma unroll
        for (int px = 0; px < 4; px++)
            #pragma unroll
            for (int q = 0; q < 4; q++) acc2[px][q] = 0ull;   // {0.f,0.f}

        for (int ct = 0; ct < 32; ct++) {
            int c0 = ct * 8;
            __syncthreads();
            {   // fill sA: 8x128 floats = 256 float4, one per thread
                int cc = tid >> 5, x4 = (tid & 31) * 4;
                *(float4*)&sA[cc][x4] =
                    *(const float4*)&cur_embed[((size_t)(b * NC + c0 + cc)) * NP + p0 + x4];
            }
            if (tid < 128) {  // fill sB: 8x64 = 128 float4
                int cc = tid >> 4, x4 = (tid & 15) * 4;
                *(float4*)&sB[cc][x4] =
                    *(const float4*)&g_fi[((size_t)(b * NC + c0 + cc)) * NK + k0 + x4];
            }
            __syncthreads();
            #pragma unroll
            for (int cc = 0; cc < 8; cc++) {
                float4 A = *(const float4*)&sA[cc][ptid * 4];
                ulonglong2 B0 = *(const ulonglong2*)&sB[cc][ktid * 8];
                ulonglong2 B1 = *(const ulonglong2*)&sB[cc][ktid * 8 + 4];
                unsigned long long ap[4];
                ap[0] = pk2(A.x, A.x); ap[1] = pk2(A.y, A.y);
                ap[2] = pk2(A.z, A.z); ap[3] = pk2(A.w, A.w);
                unsigned long long bq[4] = {B0.x, B0.y, B1.x, B1.y};
                #pragma unroll
                for (int px = 0; px < 4; px++) {
                    acc2[px][0] = f2fma(ap[px], bq[0], acc2[px][0]);
                    acc2[px][1] = f2fma(ap[px], bq[1], acc2[px][1]);
                    acc2[px][2] = f2fma(ap[px], bq[2], acc2[px][2]);
                    acc2[px][3] = f2fma(ap[px], bq[3], acc2[px][3]);
                }
            }
        }
        // fold this k-tile into the running max
        #pragma unroll
        for (int q = 0; q < 4; q++) {
            int kk = k0 + ktid * 8 + 2 * q;
            float s0a = g_si[(b * 2 + 0) * NK + kk];
            float s0b = g_si[(b * 2 + 0) * NK + kk + 1];
            float s1a = g_si[(b * 2 + 1) * NK + kk];
            float s1b = g_si[(b * 2 + 1) * NK + kk + 1];
            #pragma unroll
            for (int px = 0; px < 4; px++) {
                float lo, hi;
                upk2(acc2[px][q], lo, hi);
                m0[px] = fmaxf(m0[px], fmaxf(lo * s0a, hi * s0b));
                m1[px] = fmaxf(m1[px], fmaxf(lo * s1a, hi * s1b));
            }
        }
    }

    // reduce max across the 8 k-threads; reuse sA (1024 floats = 8x128)
    float* red = &sA[0][0];
    __syncthreads();
    #pragma unroll
    for (int i = 0; i < 4; i++) red[ktid * 128 + ptid * 4 + i] = m0[i];
    __syncthreads();
    for (int s = 4; s > 0; s >>= 1) {
        if (ktid < s)
            #pragma unroll
            for (int i = 0; i < 4; i++) {
                int px = ptid * 4 + i;
                red[ktid * 128 + px] = fmaxf(red[ktid * 128 + px], red[(ktid + s) * 128 + px]);
            }
        __syncthreads();
    }
    if (ktid == 0)
        #pragma unroll
        for (int i = 0; i < 4; i++)
            g_aux[((size_t)b * 8 + 0) * NP + p0 + ptid * 4 + i] = red[ptid * 4 + i];
    __syncthreads();
    #pragma unroll
    for (int i = 0; i < 4; i++) red[ktid * 128 + ptid * 4 + i] = m1[i];
    __syncthreads();
    for (int s = 4; s > 0; s >>= 1) {
        if (ktid < s)
            #pragma unroll
            for (int i = 0; i < 4; i++) {
                int px = ptid * 4 + i;
                red[ktid * 128 + px] = fmaxf(red[ktid * 128 + px], red[(ktid + s) * 128 + px]);
            }
        __syncthreads();
    }
    if (ktid == 0)
        #pragma unroll
        for (int i = 0; i < 4; i++)
            g_aux[((size_t)b * 8 + 1) * NP + p0 + ptid * 4 + i] = red[ptid * 4 + i];
}

// =========================================================================
// Kernel 3: local correlation (unchanged from R1 — ~4% of runtime).
// =========================================================================
__global__ void corr_kernel(const float* __restrict__ cur_embed,
                            const float* __restrict__ prev_embed,
                            const float* __restrict__ prev_seg) {
    __shared__ float prevT[8][6][40];
    int b = blockIdx.z;
    int h0 = blockIdx.y * 4;
    int w0 = blockIdx.x * 32;
    int tid = threadIdx.x;         // 128 threads
    int ty = tid >> 5, tx = tid & 31;
    int hh0 = h0 + ty, ww0 = w0 + tx;
    int p = hh0 * NW + ww0;
    float m0 = -1e30f, m1 = -1e30f;

    for (int g = 0; g < 3; g++) {
        float acc[3][9];
        #pragma unroll
        for (int r = 0; r < 3; r++)
            #pragma unroll
            for (int d = 0; d < 9; d++) acc[r][d] = 0.f;
        int hbase = h0 + g * 3 - 4;
        for (int c0 = 0; c0 < NC; c0 += 8) {
            __syncthreads();
            for (int i = tid; i < 8 * 240; i += 128) {
                int cc = i / 240, rem = i % 240, rr = rem / 40, col = rem % 40;
                int hh = hbase + rr, ww = w0 - 4 + col;
                float v = 0.f;
                if (hh >= 0 && hh < NH && ww >= 0 && ww < NW)
                    v = prev_embed[((size_t)(b * NC + c0 + cc)) * NP + hh * NW + ww];
                prevT[cc][rr][col] = v;
            }
            float cv8[8];
            #pragma unroll
            for (int cc = 0; cc < 8; cc++)
                cv8[cc] = cur_embed[((size_t)(b * NC + c0 + cc)) * NP + p];
            __syncthreads();
            #pragma unroll
            for (int cc = 0; cc < 8; cc++) {
                float cv = cv8[cc];
                #pragma unroll
                for (int r = 0; r < 3; r++)
                    #pragma unroll
                    for (int d = 0; d < 9; d++)
                        acc[r][d] += cv * prevT[cc][ty + r][tx + d];
            }
        }
        #pragma unroll
        for (int r = 0; r < 3; r++) {
            int dy = g * 3 + r - 4;
            int sh = hh0 + dy;
            #pragma unroll
            for (int d = 0; d < 9; d++) {
                int sw = ww0 + d - 4;
                if (sh >= 0 && sh < NH && sw >= 0 && sw < NW) {
                    float raw = acc[r][d] * (1.f / 256.f);
                    float s0 = prev_seg[((size_t)(b * 2 + 0)) * NP + sh * NW + sw];
                    float s1 = prev_seg[((size_t)(b * 2 + 1)) * NP + sh * NW + sw];
                    m0 = fmaxf(m0, raw * s0);
                    m1 = fmaxf(m1, raw * s1);
                } else {
                    m0 = fmaxf(m0, 0.f);
                    m1 = fmaxf(m1, 0.f);
                }
            }
        }
    }
    g_aux[((size_t)b * 8 + 4) * NP + p] = m0;
    g_aux[((size_t)b * 8 + 5) * NP + p] = m1;
}

// =========================================================================
// Kernel 4: conv1 264->128, 3x3, SAME, ReLU.  FFMA2 implicit GEMM.
// Block: 64 px (4 rows x 16 cols) x 128 oc, 256 threads.
// Thread: 4 contiguous px (sliding window) x 8 oc (2 LDS.128 -> 4 f32x2 pairs).
// =========================================================================
__global__ __launch_bounds__(256, 2) void conv1_kernel(const float* __restrict__ cur_decode,
                                                       const float* __restrict__ b1) {
    __shared__ float inT[8][6][18];       // halo tile, rows row0-1..+4, cols col0-1..+16
    __shared__ float wT[72 * 132];        // [ic*9+k][oc], row stride 132 (pad, 16B-mult)
    int b = blockIdx.z;
    int row0 = blockIdx.y * 4;
    int col0 = blockIdx.x * 16;
    int tid = threadIdx.x;
    int to = tid & 15;                    // oc group: ocs to*4+{0..3}, 64+to*4+{0..3}
    int tp = tid >> 4;                    // 16 pixel-threads
    int prow = tp >> 2;                   // 0..3
    int pcol0 = (tp & 3) * 4;             // 0,4,8,12

    unsigned long long acc2[4][4];
    #pragma unroll
    for (int px = 0; px < 4; px++)
        #pragma unroll
        for (int q = 0; q < 4; q++) acc2[px][q] = 0ull;

    for (int ic0 = 0; ic0 < 264; ic0 += 8) {
        __syncthreads();
        // input halo tile: 864 floats
        for (int i = tid; i < 864; i += 256) {
            int ic = i / 108, rem = i % 108, r = rem / 18, c2 = rem % 18;
            int hh = row0 + r - 1, ww = col0 + c2 - 1;
            float v = 0.f;
            if (hh >= 0 && hh < NH && ww >= 0 && ww < NW) {
                int icg = ic0 + ic;
                v = (icg < 256)
                        ? cur_decode[((size_t)(b * 256 + icg)) * NP + hh * NW + ww]
                        : g_aux[((size_t)b * 8 + icg - 256) * NP + hh * NW + ww];
            }
            inT[ic][r][c2] = v;
        }
        // weight tile: 72x128 floats from pre-transposed g_w1t (coalesced float4)
        {
            const float* src = &g_w1t[(size_t)ic0 * 9 * 128];
            for (int j = tid; j < 2304; j += 256) {     // 2304 float4
                int r = j >> 5, q4 = (j & 31) * 4;
                *(float4*)&wT[r * 132 + q4] = *(const float4*)&src[r * 128 + q4];
            }
        }
        __syncthreads();
        #pragma unroll
        for (int ic = 0; ic < 8; ic++) {
            #pragma unroll
            for (int ky = 0; ky < 3; ky++) {
                const float* wrow = &inT[ic][prow + ky][pcol0];
                unsigned long long ap[6];
                #pragma unroll
                for (int j = 0; j < 6; j++) { float v = wrow[j]; ap[j] = pk2(v, v); }
                #pragma unroll
                for (int kx = 0; kx < 3; kx++) {
                    const float* wr = &wT[(ic * 9 + ky * 3 + kx) * 132];
                    ulonglong2 wa = *(const ulonglong2*)&wr[to * 4];
                    ulonglong2 wb = *(const ulonglong2*)&wr[64 + to * 4];
                    unsigned long long wp0 = wa.x, wp1 = wa.y, wp2 = wb.x, wp3 = wb.y;
                    #pragma unroll
                    for (int px = 0; px < 4; px++) {
                        unsigned long long a = ap[px + kx];
                        acc2[px][0] = f2fma(a, wp0, acc2[px][0]);
                        acc2[px][1] = f2fma(a, wp1, acc2[px][1]);
                        acc2[px][2] = f2fma(a, wp2, acc2[px][2]);
                        acc2[px][3] = f2fma(a, wp3, acc2[px][3]);
                    }
                }
            }
        }
    }
    // epilogue: bias + relu + store
    int obase[4] = {to * 4, to * 4 + 2, 64 + to * 4, 64 + to * 4 + 2};
    #pragma unroll
    for (int q = 0; q < 4; q++) {
        int oc0 = obase[q];
        float ba = b1[oc0], bb = b1[oc0 + 1];
        #pragma unroll
        for (int px = 0; px < 4; px++) {
            float lo, hi;
            upk2(acc2[px][q], lo, hi);
            int p = (row0 + prow) * NW + col0 + pcol0 + px;
            g_h[((size_t)(b * 128 + oc0)) * NP + p] = fmaxf(lo + ba, 0.f);
            g_h[((size_t)(b * 128 + oc0 + 1)) * NP + p] = fmaxf(hi + bb, 0.f);
        }
    }
}

// =========================================================================
// Kernel 5: conv2 128->2, 3x3, SAME (unchanged — tiny).
// =========================================================================
__global__ void conv2_kernel(const float* __restrict__ W2,
                             const float* __restrict__ b2,
                             float* __restrict__ out) {
    __shared__ float w2s[2 * 128 * 9];
    __shared__ float hT[8][10][34];
    int b = blockIdx.z;
    int row0 = blockIdx.y * 8;
    int col0 = blockIdx.x * 32;
    int tid = threadIdx.x;
    int ty = tid >> 5, tx = tid & 31;
    for (int i = tid; i < 2304; i += 256) w2s[i] = W2[i];
    float a0 = b2[0], a1 = b2[1];

    for (int ic0 = 0; ic0 < 128; ic0 += 8) {
        __syncthreads();
        for (int i = tid; i < 8 * 340; i += 256) {
            int ic = i / 340, rem = i % 340, r = rem / 34, c2 = rem % 34;
            int hh = row0 + r - 1, ww = col0 + c2 - 1;
            float v = 0.f;
            if (hh >= 0 && hh < NH && ww >= 0 && ww < NW)
                v = g_h[((size_t)(b * 128 + ic0 + ic)) * NP + hh * NW + ww];
            hT[ic][r][c2] = v;
        }
        __syncthreads();
        #pragma unroll
        for (int ic = 0; ic < 8; ic++) {
            #pragma unroll
            for (int ky = 0; ky < 3; ky++)
                #pragma unroll
                for (int kx = 0; kx < 3; kx++) {
                    float v = hT[ic][ty + ky][tx + kx];
                    int wi = (ic0 + ic) * 9 + ky * 3 + kx;
                    a0 += v * w2s[wi];
                    a1 += v * w2s[1152 + wi];
                }
        }
    }
    int p = (row0 + ty) * NW + col0 + tx;
    out[((size_t)(b * 2 + 0)) * NP + p] = a0;
    out[((size_t)(b * 2 + 1)) * NP + p] = a1;
}

// =========================================================================
extern "C" void kernel_launch(void* const* d_in, const int* in_sizes, int n_in,
                              void* d_out, int out_size) {
    const float* cur_embed  = (const float*)d_in[0];
    const float* cur_decode = (const float*)d_in[1];
    const float* init_embed = (const float*)d_in[2];
    const float* init_seg   = (const float*)d_in[3];
    const float* prev_embed = (const float*)d_in[4];
    const float* prev_seg   = (const float*)d_in[5];
    const float* W1 = (const float*)d_in[6];
    const float* b1 = (const float*)d_in[7];
    const float* W2 = (const float*)d_in[8];
    const float* b2 = (const float*)d_in[9];
    float* out = (float*)d_out;

    int npool = NB * NC * NK + NB * 2 * NK + 2 * NB * 2 * NP + 2376 * 128;
    pool_kernel<<<(npool + 255) / 256, 256>>>(init_embed, init_seg, prev_seg, W1);
    gmap_kernel<<<dim3(NP / 128, NB), 256>>>(cur_embed);
    corr_kernel<<<dim3(NW / 32, NH / 4, NB), 128>>>(cur_embed, prev_embed, prev_seg);
    conv1_kernel<<<dim3(NW / 16, NH / 4, NB), 256>>>(cur_decode, b1);
    conv2_kernel<<<dim3(NW / 32, NH / 8, NB), 256>>>(W2, b2, out);
}

// round 7
// speedup vs baseline: 1.7689x; 1.2418x over previous
#include <cuda_runtime.h>
#include <cstdint>

// Problem constants
constexpr int NB = 8;          // batch
constexpr int NC = 256;        // embed channels
constexpr int NH = 96;
constexpr int NW = 96;
constexpr int NP = NH * NW;    // 9216 pixels
constexpr int NK = 576;        // pooled 24*24
constexpr int NHP = 24;

// ---------------- device scratch (no allocations allowed) ----------------
__device__ float g_fi[NB * NC * NK];     // pooled init_embed  (b,c,k)
__device__ float g_si[NB * 2 * NK];      // pooled init_seg    (b,2,k)
__device__ float g_aux[NB * 8 * NP];     // ch 256..263: [gmap0,gmap1,iseg0,iseg1,lmap0,lmap1,pseg0,pseg1]
__device__ float g_h[NB * 128 * NP];     // conv1 activations
__device__ float g_w1t[2376 * 128];      // W1 transposed: [(ic*9+k)][oc]

// ---------------- packed f32x2 helpers (Blackwell FFMA2) ----------------
__device__ __forceinline__ unsigned long long pk2(float lo, float hi) {
    unsigned long long r;
    asm("mov.b64 %0,{%1,%2};" : "=l"(r) : "f"(lo), "f"(hi));
    return r;
}
__device__ __forceinline__ unsigned long long f2fma(unsigned long long a,
                                                    unsigned long long b,
                                                    unsigned long long c) {
    unsigned long long d;
    asm("fma.rn.f32x2 %0,%1,%2,%3;" : "=l"(d) : "l"(a), "l"(b), "l"(c));
    return d;
}
__device__ __forceinline__ void upk2(unsigned long long p, float& lo, float& hi) {
    asm("mov.b64 {%0,%1},%2;" : "=f"(lo), "=f"(hi) : "l"(p));
}

// ---------------- cp.async helpers (sm_80+, fine on compute_100) ---------
__device__ __forceinline__ uint32_t smem_u32(const void* p) {
    uint32_t a;
    asm("{ .reg .u64 t; cvta.to.shared.u64 t, %1; cvt.u32.u64 %0, t; }"
        : "=r"(a) : "l"(p));
    return a;
}
__device__ __forceinline__ void cpa16(uint32_t dst, const void* src) {
    asm volatile("cp.async.ca.shared.global [%0],[%1],16;" :: "r"(dst), "l"(src));
}
// 4-byte copy with zero-fill when sz==0 (src must still be a valid address)
__device__ __forceinline__ void cpa4z(uint32_t dst, const void* src, int sz) {
    asm volatile("cp.async.ca.shared.global [%0],[%1],4,%2;"
                 :: "r"(dst), "l"(src), "r"(sz));
}
#define CP_COMMIT() asm volatile("cp.async.commit_group;" ::: "memory")
#define CP_WAIT1()  asm volatile("cp.async.wait_group 1;" ::: "memory")
#define CP_WAIT0()  asm volatile("cp.async.wait_group 0;" ::: "memory")

// =========================================================================
// Kernel 1: avg_pool4 (init_embed -> g_fi, init_seg -> g_si), seg copies
// into aux channels, and one-time W1 transpose into g_w1t.
// =========================================================================
__global__ void pool_kernel(const float* __restrict__ init_embed,
                            const float* __restrict__ init_seg,
                            const float* __restrict__ prev_seg,
                            const float* __restrict__ W1) {
    int idx = blockIdx.x * blockDim.x + threadIdx.x;
    const int NFI = NB * NC * NK;
    const int NSI = NB * 2 * NK;
    const int NCP = NB * 2 * NP;
    const int NWT = 2376 * 128;
    if (idx < NFI) {
        int b = idx / (NC * NK);
        int r = idx % (NC * NK);
        int c = r / NK;
        int k = r % NK;
        int hp = k / NHP, wp = k % NHP;
        const float* src = init_embed + ((size_t)(b * NC + c) * NH + hp * 4) * NW + wp * 4;
        float s = 0.f;
        #pragma unroll
        for (int i = 0; i < 4; i++)
            #pragma unroll
            for (int j = 0; j < 4; j++) s += src[i * NW + j];
        g_fi[idx] = s * (1.f / 16.f);
    } else if (idx < NFI + NSI) {
        int t = idx - NFI;
        int b = t / (2 * NK);
        int r = t % (2 * NK);
        int c = r / NK;
        int k = r % NK;
        int hp = k / NHP, wp = k % NHP;
        const float* src = init_seg + ((size_t)(b * 2 + c) * NH + hp * 4) * NW + wp * 4;
        float s = 0.f;
        #pragma unroll
        for (int i = 0; i < 4; i++)
            #pragma unroll
            for (int j = 0; j < 4; j++) s += src[i * NW + j];
        g_si[t] = s * (1.f / 16.f);
    } else if (idx < NFI + NSI + 2 * NCP) {
        int t = idx - NFI - NSI;
        int which = t / NCP;            // 0: init_seg -> aux[2,3]; 1: prev_seg -> aux[6,7]
        int r = t % NCP;
        int b = r / (2 * NP);
        int rem = r % (2 * NP);
        int c = rem / NP;
        int p = rem % NP;
        float v = which ? prev_seg[r] : init_seg[r];
        g_aux[((size_t)b * 8 + (which ? 6 : 2) + c) * NP + p] = v;
    } else if (idx < NFI + NSI + 2 * NCP + NWT) {
        int t = idx - NFI - NSI - 2 * NCP;   // t = r*128 + oc  (coalesced writes)
        int r = t >> 7;
        int oc = t & 127;
        g_w1t[t] = W1[(size_t)oc * 2376 + r];
    }
}

// =========================================================================
// Kernel 2: global map.  sim[k,p] = sum_c fi[c,k]*cur[c,p];
// gmap[cls,p] = max_k sim[k,p]*si[cls,k].
// Block 128px x 64k, 256 thr (32 px-thr x 8 k-thr), thread 4px x 8k FFMA2.
// cp.async double-buffered 8-channel chunks; q = kt*32+ct linear pipeline.
// =========================================================================
__global__ __launch_bounds__(256) void gmap_kernel(const float* __restrict__ cur_embed) {
    __shared__ __align__(16) float sA[2][1024];   // [buf][cc*128+px]
    __shared__ __align__(16) float sB[2][512];    // [buf][cc*64+k]
    __shared__ __align__(16) float sSi[1152];     // si[2][576] for this batch
    __shared__ float red[8 * 132];
    int tid = threadIdx.x;
    int ktid = tid & 7;        // 8 k-threads, each 8 k
    int ptid = tid >> 3;       // 32 px-threads, each 4 px
    int b = blockIdx.y;
    int p0 = blockIdx.x * 128;

    uint32_t aA = smem_u32(&sA[0][0]);
    uint32_t aB = smem_u32(&sB[0][0]);
    uint32_t aSi = smem_u32(&sSi[0]);

    // chunk fill: q = kt*32+ct.  A depends only on ct; B on (kt,ct).
    auto fillchunk = [&](int q) {
        int kt = q >> 5, ct = q & 31, sel = q & 1;
        {   // A: 8c x 128px = 256 float4, 1 per thread
            int cc = tid >> 5, x4 = (tid & 31) * 4;
            cpa16(aA + (uint32_t)(sel * 1024 + cc * 128 + x4) * 4,
                  &cur_embed[((size_t)(b * NC + ct * 8 + cc)) * NP + p0 + x4]);
        }
        if (tid < 128) {   // B: 8c x 64k = 128 float4
            int cc = tid >> 4, x4 = (tid & 15) * 4;
            cpa16(aB + (uint32_t)(sel * 512 + cc * 64 + x4) * 4,
                  &g_fi[((size_t)(b * NC + ct * 8 + cc)) * NK + kt * 64 + x4]);
        }
    };

    // prologue group: si + chunk 0
    for (int i = tid; i < 1152; i += 256)
        cpa4z(aSi + (uint32_t)i * 4, &g_si[b * 2 * NK + i], 4);
    fillchunk(0);
    CP_COMMIT();

    float m0[4], m1[4];
    #pragma unroll
    for (int i = 0; i < 4; i++) { m0[i] = -1e30f; m1[i] = -1e30f; }
    unsigned long long acc2[4][4];

    for (int q = 0; q < 288; q++) {
        int kt = q >> 5, ct = q & 31, sel = q & 1;
        if (q < 287) { fillchunk(q + 1); CP_COMMIT(); CP_WAIT1(); }
        else CP_WAIT0();
        __syncthreads();
        if (ct == 0) {
            #pragma unroll
            for (int px = 0; px < 4; px++)
                #pragma unroll
                for (int qq = 0; qq < 4; qq++) acc2[px][qq] = 0ull;
        }
        const float* A = sA[sel];
        const float* B = sB[sel];
        #pragma unroll
        for (int cc = 0; cc < 8; cc++) {
            float4 Av = *(const float4*)&A[cc * 128 + ptid * 4];
            ulonglong2 B0 = *(const ulonglong2*)&B[cc * 64 + ktid * 8];
            ulonglong2 B1 = *(const ulonglong2*)&B[cc * 64 + ktid * 8 + 4];
            unsigned long long ap[4];
            ap[0] = pk2(Av.x, Av.x); ap[1] = pk2(Av.y, Av.y);
            ap[2] = pk2(Av.z, Av.z); ap[3] = pk2(Av.w, Av.w);
            unsigned long long bq[4] = {B0.x, B0.y, B1.x, B1.y};
            #pragma unroll
            for (int px = 0; px < 4; px++) {
                acc2[px][0] = f2fma(ap[px], bq[0], acc2[px][0]);
                acc2[px][1] = f2fma(ap[px], bq[1], acc2[px][1]);
                acc2[px][2] = f2fma(ap[px], bq[2], acc2[px][2]);
                acc2[px][3] = f2fma(ap[px], bq[3], acc2[px][3]);
            }
        }
        if (ct == 31) {   // fold this k-tile into the running max
            #pragma unroll
            for (int qq = 0; qq < 4; qq++) {
                int kk = kt * 64 + ktid * 8 + 2 * qq;
                float s0a = sSi[kk], s0b = sSi[kk + 1];
                float s1a = sSi[NK + kk], s1b = sSi[NK + kk + 1];
                #pragma unroll
                for (int px = 0; px < 4; px++) {
                    float lo, hi;
                    upk2(acc2[px][qq], lo, hi);
                    m0[px] = fmaxf(m0[px], fmaxf(lo * s0a, hi * s0b));
                    m1[px] = fmaxf(m1[px], fmaxf(lo * s1a, hi * s1b));
                }
            }
        }
        __syncthreads();
    }

    // reduce max across the 8 k-threads per pixel, per class
    #pragma unroll
    for (int i = 0; i < 4; i++) red[ktid * 132 + ptid * 4 + i] = m0[i];
    __syncthreads();
    for (int s = 4; s > 0; s >>= 1) {
        if (ktid < s)
            #pragma unroll
            for (int i = 0; i < 4; i++) {
                int px = ptid * 4 + i;
                red[ktid * 132 + px] = fmaxf(red[ktid * 132 + px], red[(ktid + s) * 132 + px]);
            }
        __syncthreads();
    }
    if (ktid == 0)
        #pragma unroll
        for (int i = 0; i < 4; i++)
            g_aux[((size_t)b * 8 + 0) * NP + p0 + ptid * 4 + i] = red[ptid * 4 + i];
    __syncthreads();
    #pragma unroll
    for (int i = 0; i < 4; i++) red[ktid * 132 + ptid * 4 + i] = m1[i];
    __syncthreads();
    for (int s = 4; s > 0; s >>= 1) {
        if (ktid < s)
            #pragma unroll
            for (int i = 0; i < 4; i++) {
                int px = ptid * 4 + i;
                red[ktid * 132 + px] = fmaxf(red[ktid * 132 + px], red[(ktid + s) * 132 + px]);
            }
        __syncthreads();
    }
    if (ktid == 0)
        #pragma unroll
        for (int i = 0; i < 4; i++)
            g_aux[((size_t)b * 8 + 1) * NP + p0 + ptid * 4 + i] = red[ptid * 4 + i];
}

// =========================================================================
// Kernel 3: local correlation, cp.async double-buffered prev tiles.
// raw(p,d) = sum_c cur[c,p]*prev[c,p+d]/C ; lmap = max_d raw*seg(p+d).
// =========================================================================
__global__ void corr_kernel(const float* __restrict__ cur_embed,
                            const float* __restrict__ prev_embed,
                            const float* __restrict__ prev_seg) {
    __shared__ __align__(16) float prevT[2][1920];   // [buf][cc*240 + rr*40 + col]
    int b = blockIdx.z;
    int h0 = blockIdx.y * 4;
    int w0 = blockIdx.x * 32;
    int tid = threadIdx.x;         // 128 threads
    int ty = tid >> 5, tx = tid & 31;
    int hh0 = h0 + ty, ww0 = w0 + tx;
    int p = hh0 * NW + ww0;
    float m0 = -1e30f, m1 = -1e30f;
    uint32_t aP = smem_u32(&prevT[0][0]);

    for (int g = 0; g < 3; g++) {
        int hbase = h0 + g * 3 - 4;
        auto fill = [&](int chunk) {
            int sel = chunk & 1, c0 = chunk * 8;
            for (int i = tid; i < 1920; i += 128) {
                int cc = i / 240, rem = i % 240, rr = rem / 40, col = rem % 40;
                int hh = hbase + rr, ww = w0 - 4 + col;
                bool ok = (hh >= 0 && hh < NH && ww >= 0 && ww < NW);
                const float* src = ok
                    ? &prev_embed[((size_t)(b * NC + c0 + cc)) * NP + hh * NW + ww]
                    : prev_embed;
                cpa4z(aP + (uint32_t)(sel * 1920 + i) * 4, src, ok ? 4 : 0);
            }
        };
        float acc[3][9];
        #pragma unroll
        for (int r = 0; r < 3; r++)
            #pragma unroll
            for (int d = 0; d < 9; d++) acc[r][d] = 0.f;

        fill(0);
        CP_COMMIT();
        for (int ch = 0; ch < 32; ch++) {
            if (ch < 31) { fill(ch + 1); CP_COMMIT(); CP_WAIT1(); }
            else CP_WAIT0();
            float cv8[8];
            #pragma unroll
            for (int cc = 0; cc < 8; cc++)
                cv8[cc] = cur_embed[((size_t)(b * NC + ch * 8 + cc)) * NP + p];
            __syncthreads();
            const float* P = prevT[ch & 1];
            #pragma unroll
            for (int cc = 0; cc < 8; cc++) {
                float cv = cv8[cc];
                const float* Pr = &P[cc * 240];
                #pragma unroll
                for (int r = 0; r < 3; r++)
                    #pragma unroll
                    for (int d = 0; d < 9; d++)
                        acc[r][d] += cv * Pr[(ty + r) * 40 + tx + d];
            }
            __syncthreads();
        }
        #pragma unroll
        for (int r = 0; r < 3; r++) {
            int dy = g * 3 + r - 4;
            int sh = hh0 + dy;
            #pragma unroll
            for (int d = 0; d < 9; d++) {
                int sw = ww0 + d - 4;
                if (sh >= 0 && sh < NH && sw >= 0 && sw < NW) {
                    float raw = acc[r][d] * (1.f / 256.f);
                    float s0 = prev_seg[((size_t)(b * 2 + 0)) * NP + sh * NW + sw];
                    float s1 = prev_seg[((size_t)(b * 2 + 1)) * NP + sh * NW + sw];
                    m0 = fmaxf(m0, raw * s0);
                    m1 = fmaxf(m1, raw * s1);
                } else {
                    m0 = fmaxf(m0, 0.f);   // zero-padded masked feats -> corr = 0
                    m1 = fmaxf(m1, 0.f);
                }
            }
        }
    }
    g_aux[((size_t)b * 8 + 4) * NP + p] = m0;
    g_aux[((size_t)b * 8 + 5) * NP + p] = m1;
}

// =========================================================================
// Kernel 4: conv1 264->128, 3x3, SAME, ReLU.  FFMA2 8px x 8oc per thread,
// cp.async double-buffered 4-channel chunks (66 chunks).
// Block: 128 px (4 rows x 32 cols) x 128 oc, 256 threads.
// =========================================================================
__global__ __launch_bounds__(256, 2) void conv1_kernel(const float* __restrict__ cur_decode,
                                                       const float* __restrict__ b1) {
    __shared__ __align__(16) float inT[2][816];    // 4ic x 6 x 34
    __shared__ __align__(16) float wT[2][36 * 132]; // [(ic*9+k)][oc] pad 132
    int b = blockIdx.z;
    int row0 = blockIdx.y * 4;
    int col0 = blockIdx.x * 32;
    int tid = threadIdx.x;
    int to = tid & 15;                    // oc group
    int tp = tid >> 4;                    // 16 pixel-threads
    int prow = tp >> 2;                   // 0..3
    int pcol0 = (tp & 3) * 8;             // 0,8,16,24
    uint32_t aI = smem_u32(&inT[0][0]);
    uint32_t aW = smem_u32(&wT[0][0]);

    auto fill = [&](int ci) {
        int sel = ci & 1, ic0 = ci * 4;
        // input halo tile: 816 scalars (zfill OOB)
        for (int i = tid; i < 816; i += 256) {
            int ic = i / 204, rem = i % 204, r = rem / 34, c2 = rem % 34;
            int hh = row0 + r - 1, ww = col0 + c2 - 1;
            bool ok = (hh >= 0 && hh < NH && ww >= 0 && ww < NW);
            int icg = ic0 + ic;
            const float* src;
            if (!ok) src = cur_decode;
            else if (icg < 256) src = &cur_decode[((size_t)(b * 256 + icg)) * NP + hh * NW + ww];
            else src = &g_aux[((size_t)b * 8 + icg - 256) * NP + hh * NW + ww];
            cpa4z(aI + (uint32_t)(sel * 816 + i) * 4, src, ok ? 4 : 0);
        }
        // weights: 36 rows x 128 oc = 1152 float4
        for (int j = tid; j < 1152; j += 256) {
            int r = j >> 5, q4 = (j & 31) * 4;
            cpa16(aW + (uint32_t)(sel * 4752 + r * 132 + q4) * 4,
                  &g_w1t[(size_t)(ic0 * 9 + r) * 128 + q4]);
        }
    };

    unsigned long long acc2[8][4];
    #pragma unroll
    for (int px = 0; px < 8; px++)
        #pragma unroll
        for (int q = 0; q < 4; q++) acc2[px][q] = 0ull;

    fill(0);
    CP_COMMIT();
    for (int ci = 0; ci < 66; ci++) {
        if (ci < 65) { fill(ci + 1); CP_COMMIT(); CP_WAIT1(); }
        else CP_WAIT0();
        __syncthreads();
        int sel = ci & 1;
        const float* I = inT[sel];
        const float* W = wT[sel];
        #pragma unroll
        for (int ic = 0; ic < 4; ic++) {
            #pragma unroll
            for (int ky = 0; ky < 3; ky++) {
                const float* wrow = &I[ic * 204 + (prow + ky) * 34 + pcol0];
                unsigned long long ap[10];
                #pragma unroll
                for (int j = 0; j < 10; j++) { float v = wrow[j]; ap[j] = pk2(v, v); }
                #pragma unroll
                for (int kx = 0; kx < 3; kx++) {
                    const float* wr = &W[(ic * 9 + ky * 3 + kx) * 132];
                    ulonglong2 wa = *(const ulonglong2*)&wr[to * 4];
                    ulonglong2 wb = *(const ulonglong2*)&wr[64 + to * 4];
                    unsigned long long wp0 = wa.x, wp1 = wa.y, wp2 = wb.x, wp3 = wb.y;
                    #pragma unroll
                    for (int px = 0; px < 8; px++) {
                        unsigned long long a = ap[px + kx];
                        acc2[px][0] = f2fma(a, wp0, acc2[px][0]);
                        acc2[px][1] = f2fma(a, wp1, acc2[px][1]);
                        acc2[px][2] = f2fma(a, wp2, acc2[px][2]);
                        acc2[px][3] = f2fma(a, wp3, acc2[px][3]);
                    }
                }
            }
        }
        __syncthreads();
    }
    // epilogue: bias + relu + store
    int obase[4] = {to * 4, to * 4 + 2, 64 + to * 4, 64 + to * 4 + 2};
    #pragma unroll
    for (int q = 0; q < 4; q++) {
        int oc0 = obase[q];
        float ba = b1[oc0], bb = b1[oc0 + 1];
        #pragma unroll
        for (int px = 0; px < 8; px++) {
            float lo, hi;
            upk2(acc2[px][q], lo, hi);
            int p = (row0 + prow) * NW + col0 + pcol0 + px;
            g_h[((size_t)(b * 128 + oc0)) * NP + p] = fmaxf(lo + ba, 0.f);
            g_h[((size_t)(b * 128 + oc0 + 1)) * NP + p] = fmaxf(hi + bb, 0.f);
        }
    }
}

// =========================================================================
// Kernel 5: conv2 128->2, 3x3, SAME (small).
// =========================================================================
__global__ void conv2_kernel(const float* __restrict__ W2,
                             const float* __restrict__ b2,
                             float* __restrict__ out) {
    __shared__ float w2s[2 * 128 * 9];
    __shared__ float hT[8][10][34];
    int b = blockIdx.z;
    int row0 = blockIdx.y * 8;
    int col0 = blockIdx.x * 32;
    int tid = threadIdx.x;
    int ty = tid >> 5, tx = tid & 31;
    for (int i = tid; i < 2304; i += 256) w2s[i] = W2[i];
    float a0 = b2[0], a1 = b2[1];

    for (int ic0 = 0; ic0 < 128; ic0 += 8) {
        __syncthreads();
        for (int i = tid; i < 8 * 340; i += 256) {
            int ic = i / 340, rem = i % 340, r = rem / 34, c2 = rem % 34;
            int hh = row0 + r - 1, ww = col0 + c2 - 1;
            float v = 0.f;
            if (hh >= 0 && hh < NH && ww >= 0 && ww < NW)
                v = g_h[((size_t)(b * 128 + ic0 + ic)) * NP + hh * NW + ww];
            hT[ic][r][c2] = v;
        }
        __syncthreads();
        #pragma unroll
        for (int ic = 0; ic < 8; ic++) {
            #pragma unroll
            for (int ky = 0; ky < 3; ky++)
                #pragma unroll
                for (int kx = 0; kx < 3; kx++) {
                    float v = hT[ic][ty + ky][tx + kx];
                    int wi = (ic0 + ic) * 9 + ky * 3 + kx;
                    a0 += v * w2s[wi];
                    a1 += v * w2s[1152 + wi];
                }
        }
    }
    int p = (row0 + ty) * NW + col0 + tx;
    out[((size_t)(b * 2 + 0)) * NP + p] = a0;
    out[((size_t)(b * 2 + 1)) * NP + p] = a1;
}

// =========================================================================
extern "C" void kernel_launch(void* const* d_in, const int* in_sizes, int n_in,
                              void* d_out, int out_size) {
    const float* cur_embed  = (const float*)d_in[0];
    const float* cur_decode = (const float*)d_in[1];
    const float* init_embed = (const float*)d_in[2];
    const float* init_seg   = (const float*)d_in[3];
    const float* prev_embed = (const float*)d_in[4];
    const float* prev_seg   = (const float*)d_in[5];
    const float* W1 = (const float*)d_in[6];
    const float* b1 = (const float*)d_in[7];
    const float* W2 = (const float*)d_in[8];
    const float* b2 = (const float*)d_in[9];
    float* out = (float*)d_out;

    int npool = NB * NC * NK + NB * 2 * NK + 2 * NB * 2 * NP + 2376 * 128;
    pool_kernel<<<(npool + 255) / 256, 256>>>(init_embed, init_seg, prev_seg, W1);
    gmap_kernel<<<dim3(NP / 128, NB), 256>>>(cur_embed);
    corr_kernel<<<dim3(NW / 32, NH / 4, NB), 128>>>(cur_embed, prev_embed, prev_seg);
    conv1_kernel<<<dim3(NW / 32, NH / 4, NB), 256>>>(cur_decode, b1);
    conv2_kernel<<<dim3(NW / 32, NH / 8, NB), 256>>>(W2, b2, out);
}

// round 8
// speedup vs baseline: 2.0517x; 1.1599x over previous
#include <cuda_runtime.h>
#include <cstdint>

// Problem constants
constexpr int NB = 8;          // batch
constexpr int NC = 256;        // embed channels
constexpr int NH = 96;
constexpr int NW = 96;
constexpr int NP = NH * NW;    // 9216 pixels
constexpr int NK = 576;        // pooled 24*24
constexpr int NHP = 24;

// ---------------- device scratch (no allocations allowed) ----------------
__device__ float g_fi[NB * NC * NK];     // pooled init_embed  (b,c,k)
__device__ float g_si[NB * 2 * NK];      // pooled init_seg    (b,2,k)
__device__ float g_aux[NB * 8 * NP];     // ch 256..263: [gmap0,gmap1,iseg0,iseg1,lmap0,lmap1,pseg0,pseg1]
__device__ float g_h[NB * 128 * NP];     // conv1 activations
__device__ float g_w1t[2376 * 128];      // W1 transposed: [(ic*9+k)][oc]

// ---------------- packed f32x2 helpers (Blackwell FFMA2) ----------------
__device__ __forceinline__ unsigned long long pk2(float lo, float hi) {
    unsigned long long r;
    asm("mov.b64 %0,{%1,%2};" : "=l"(r) : "f"(lo), "f"(hi));
    return r;
}
__device__ __forceinline__ unsigned long long f2fma(unsigned long long a,
                                                    unsigned long long b,
                                                    unsigned long long c) {
    unsigned long long d;
    asm("fma.rn.f32x2 %0,%1,%2,%3;" : "=l"(d) : "l"(a), "l"(b), "l"(c));
    return d;
}
__device__ __forceinline__ void upk2(unsigned long long p, float& lo, float& hi) {
    asm("mov.b64 {%0,%1},%2;" : "=f"(lo), "=f"(hi) : "l"(p));
}

// ---------------- cp.async helpers ----------------
__device__ __forceinline__ uint32_t smem_u32(const void* p) {
    uint32_t a;
    asm("{ .reg .u64 t; cvta.to.shared.u64 t, %1; cvt.u32.u64 %0, t; }"
        : "=r"(a) : "l"(p));
    return a;
}
__device__ __forceinline__ void cpa16(uint32_t dst, const void* src) {
    asm volatile("cp.async.ca.shared.global [%0],[%1],16;" :: "r"(dst), "l"(src));
}
// 16-byte copy with zero-fill when sz==0 (src must still be a valid address)
__device__ __forceinline__ void cpa16z(uint32_t dst, const void* src, int sz) {
    asm volatile("cp.async.ca.shared.global [%0],[%1],16,%2;"
                 :: "r"(dst), "l"(src), "r"(sz));
}
// 4-byte copy with zero-fill when sz==0
__device__ __forceinline__ void cpa4z(uint32_t dst, const void* src, int sz) {
    asm volatile("cp.async.ca.shared.global [%0],[%1],4,%2;"
                 :: "r"(dst), "l"(src), "r"(sz));
}
#define CP_COMMIT() asm volatile("cp.async.commit_group;" ::: "memory")
#define CP_WAIT1()  asm volatile("cp.async.wait_group 1;" ::: "memory")
#define CP_WAIT0()  asm volatile("cp.async.wait_group 0;" ::: "memory")

// =========================================================================
// Kernel 1: avg_pool4 (init_embed -> g_fi, init_seg -> g_si), seg copies
// into aux channels, and one-time W1 transpose into g_w1t.
// =========================================================================
__global__ void pool_kernel(const float* __restrict__ init_embed,
                            const float* __restrict__ init_seg,
                            const float* __restrict__ prev_seg,
                            const float* __restrict__ W1) {
    int idx = blockIdx.x * blockDim.x + threadIdx.x;
    const int NFI = NB * NC * NK;
    const int NSI = NB * 2 * NK;
    const int NCP = NB * 2 * NP;
    const int NWT = 2376 * 128;
    if (idx < NFI) {
        int b = idx / (NC * NK);
        int r = idx % (NC * NK);
        int c = r / NK;
        int k = r % NK;
        int hp = k / NHP, wp = k % NHP;
        const float* src = init_embed + ((size_t)(b * NC + c) * NH + hp * 4) * NW + wp * 4;
        float s = 0.f;
        #pragma unroll
        for (int i = 0; i < 4; i++)
            #pragma unroll
            for (int j = 0; j < 4; j++) s += src[i * NW + j];
        g_fi[idx] = s * (1.f / 16.f);
    } else if (idx < NFI + NSI) {
        int t = idx - NFI;
        int b = t / (2 * NK);
        int r = t % (2 * NK);
        int c = r / NK;
        int k = r % NK;
        int hp = k / NHP, wp = k % NHP;
        const float* src = init_seg + ((size_t)(b * 2 + c) * NH + hp * 4) * NW + wp * 4;
        float s = 0.f;
        #pragma unroll
        for (int i = 0; i < 4; i++)
            #pragma unroll
            for (int j = 0; j < 4; j++) s += src[i * NW + j];
        g_si[t] = s * (1.f / 16.f);
    } else if (idx < NFI + NSI + 2 * NCP) {
        int t = idx - NFI - NSI;
        int which = t / NCP;            // 0: init_seg -> aux[2,3]; 1: prev_seg -> aux[6,7]
        int r = t % NCP;
        int b = r / (2 * NP);
        int rem = r % (2 * NP);
        int c = rem / NP;
        int p = rem % NP;
        float v = which ? prev_seg[r] : init_seg[r];
        g_aux[((size_t)b * 8 + (which ? 6 : 2) + c) * NP + p] = v;
    } else if (idx < NFI + NSI + 2 * NCP + NWT) {
        int t = idx - NFI - NSI - 2 * NCP;   // t = r*128 + oc  (coalesced writes)
        int r = t >> 7;
        int oc = t & 127;
        g_w1t[t] = W1[(size_t)oc * 2376 + r];
    }
}

// =========================================================================
// Kernel 2: global map.  sim[k,p] = sum_c fi[c,k]*cur[c,p];
// gmap[cls,p] = max_k sim[k,p]*si[cls,k].
// Block 128px x 64k, 256 thr (32 px-thr x 8 k-thr), thread 4px x 8k FFMA2.
// 16-channel chunks, 3-stage cp.async pipeline, ONE syncthreads per chunk.
// it = kt*16 + ct : 9 k-tiles x 16 channel-chunks = 144 iterations.
// =========================================================================
__global__ __launch_bounds__(256) void gmap_kernel(const float* __restrict__ cur_embed) {
    __shared__ __align__(16) float sA[3 * 2048];   // [sel][cc*128+px], 16 cc
    __shared__ __align__(16) float sB[3 * 1024];   // [sel][cc*64+k]
    __shared__ __align__(16) float sSi[1152];      // si[2][576] for this batch
    __shared__ float red[8 * 132];
    int tid = threadIdx.x;
    int ktid = tid & 7;        // 8 k-threads, each 8 k
    int ptid = tid >> 3;       // 32 px-threads, each 4 px
    int b = blockIdx.y;
    int p0 = blockIdx.x * 128;

    uint32_t aA = smem_u32(&sA[0]);
    uint32_t aB = smem_u32(&sB[0]);
    uint32_t aSi = smem_u32(&sSi[0]);

    auto fillchunk = [&](int it) {
        int kt = it >> 4, ct = it & 15, sel = it % 3;
        int c0 = ct * 16;
        uint32_t basA = aA + (uint32_t)(sel * 2048) * 4;
        uint32_t basB = aB + (uint32_t)(sel * 1024) * 4;
        #pragma unroll
        for (int r = 0; r < 2; r++) {            // A: 512 float4
            int i = tid + r * 256;
            int cc = i >> 5, x4 = (i & 31) * 4;
            cpa16(basA + (uint32_t)(cc * 128 + x4) * 4,
                  &cur_embed[((size_t)(b * NC + c0 + cc)) * NP + p0 + x4]);
        }
        {                                        // B: 256 float4
            int cc = tid >> 4, x4 = (tid & 15) * 4;
            cpa16(basB + (uint32_t)(cc * 64 + x4) * 4,
                  &g_fi[((size_t)(b * NC + c0 + cc)) * NK + kt * 64 + x4]);
        }
    };

    // prologue: group0 = si + chunk0 ; group1 = chunk1
    for (int i = tid; i < 1152; i += 256)
        cpa4z(aSi + (uint32_t)i * 4, &g_si[b * 2 * NK + i], 4);
    fillchunk(0);
    CP_COMMIT();
    fillchunk(1);
    CP_COMMIT();

    float m0[4], m1[4];
    #pragma unroll
    for (int i = 0; i < 4; i++) { m0[i] = -1e30f; m1[i] = -1e30f; }
    unsigned long long acc2[4][4];

    for (int it = 0; it < 144; it++) {
        int kt = it >> 4, ct = it & 15, sel = it % 3;
        if (it < 143) CP_WAIT1(); else CP_WAIT0();
        __syncthreads();                       // fill(it) visible; compute(it-1) done
        if (it + 2 < 144) { fillchunk(it + 2); CP_COMMIT(); }
        if (ct == 0) {
            #pragma unroll
            for (int px = 0; px < 4; px++)
                #pragma unroll
                for (int qq = 0; qq < 4; qq++) acc2[px][qq] = 0ull;
        }
        const float* A = &sA[sel * 2048];
        const float* B = &sB[sel * 1024];
        #pragma unroll
        for (int cc = 0; cc < 16; cc++) {
            float4 Av = *(const float4*)&A[cc * 128 + ptid * 4];
            ulonglong2 B0 = *(const ulonglong2*)&B[cc * 64 + ktid * 8];
            ulonglong2 B1 = *(const ulonglong2*)&B[cc * 64 + ktid * 8 + 4];
            unsigned long long ap[4];
            ap[0] = pk2(Av.x, Av.x); ap[1] = pk2(Av.y, Av.y);
            ap[2] = pk2(Av.z, Av.z); ap[3] = pk2(Av.w, Av.w);
            unsigned long long bq[4] = {B0.x, B0.y, B1.x, B1.y};
            #pragma unroll
            for (int px = 0; px < 4; px++) {
                acc2[px][0] = f2fma(ap[px], bq[0], acc2[px][0]);
                acc2[px][1] = f2fma(ap[px], bq[1], acc2[px][1]);
                acc2[px][2] = f2fma(ap[px], bq[2], acc2[px][2]);
                acc2[px][3] = f2fma(ap[px], bq[3], acc2[px][3]);
            }
        }
        if (ct == 15) {   // fold this k-tile into the running max
            #pragma unroll
            for (int qq = 0; qq < 4; qq++) {
                int kk = kt * 64 + ktid * 8 + 2 * qq;
                float s0a = sSi[kk], s0b = sSi[kk + 1];
                float s1a = sSi[NK + kk], s1b = sSi[NK + kk + 1];
                #pragma unroll
                for (int px = 0; px < 4; px++) {
                    float lo, hi;
                    upk2(acc2[px][qq], lo, hi);
                    m0[px] = fmaxf(m0[px], fmaxf(lo * s0a, hi * s0b));
                    m1[px] = fmaxf(m1[px], fmaxf(lo * s1a, hi * s1b));
                }
            }
        }
    }

    // reduce max across the 8 k-threads per pixel, per class
    __syncthreads();
    #pragma unroll
    for (int i = 0; i < 4; i++) red[ktid * 132 + ptid * 4 + i] = m0[i];
    __syncthreads();
    for (int s = 4; s > 0; s >>= 1) {
        if (ktid < s)
            #pragma unroll
            for (int i = 0; i < 4; i++) {
                int px = ptid * 4 + i;
                red[ktid * 132 + px] = fmaxf(red[ktid * 132 + px], red[(ktid + s) * 132 + px]);
            }
        __syncthreads();
    }
    if (ktid == 0)
        #pragma unroll
        for (int i = 0; i < 4; i++)
            g_aux[((size_t)b * 8 + 0) * NP + p0 + ptid * 4 + i] = red[ptid * 4 + i];
    __syncthreads();
    #pragma unroll
    for (int i = 0; i < 4; i++) red[ktid * 132 + ptid * 4 + i] = m1[i];
    __syncthreads();
    for (int s = 4; s > 0; s >>= 1) {
        if (ktid < s)
            #pragma unroll
            for (int i = 0; i < 4; i++) {
                int px = ptid * 4 + i;
                red[ktid * 132 + px] = fmaxf(red[ktid * 132 + px], red[(ktid + s) * 132 + px]);
            }
        __syncthreads();
    }
    if (ktid == 0)
        #pragma unroll
        for (int i = 0; i < 4; i++)
            g_aux[((size_t)b * 8 + 1) * NP + p0 + ptid * 4 + i] = red[ptid * 4 + i];
}

// =========================================================================
// Kernel 3: local correlation, single 12-row halo, all-81 accumulators.
// raw(p,d) = sum_c cur[c,p]*prev[c,p+d]/C ; lmap = max_d raw*seg(p+d).
// OOB displacements: prev halo zero-filled -> raw=0; seg smem zero-filled
// -> contribution 0 (matches the reference's zero-pad + max).
// 128 threads = 4x32 pixel tile; 32 channel-chunks of 8, N=2 pipeline.
// =========================================================================
__global__ __launch_bounds__(128) void corr_kernel(const float* __restrict__ cur_embed,
                                                   const float* __restrict__ prev_embed,
                                                   const float* __restrict__ prev_seg) {
    __shared__ __align__(16) float prevT[2 * 3840];  // [sel][cc*480 + rr*40 + col]
    __shared__ __align__(16) float curS[2 * 1024];   // [sel][cc*128 + tid]
    __shared__ __align__(16) float segS[960];        // [cls*480 + rr*40 + col]
    int b = blockIdx.z;
    int h0 = blockIdx.y * 4;
    int w0 = blockIdx.x * 32;
    int tid = threadIdx.x;
    int ty = tid >> 5, tx = tid & 31;
    uint32_t aP = smem_u32(&prevT[0]);
    uint32_t aC = smem_u32(&curS[0]);
    uint32_t aS = smem_u32(&segS[0]);

    // halo rows h0-4 .. h0+7 (12), cols w0-4 .. w0+35 (40, 16B-aligned groups)
    auto fill = [&](int ch) {
        int sel = ch & 1, c0 = ch * 8;
        for (int i = tid; i < 960; i += 128) {       // prev: 960 float4
            int cc = i / 120, rem = i % 120, rr = rem / 10, j4 = (rem % 10) * 4;
            int hh = h0 - 4 + rr, ww = w0 - 4 + j4;
            bool ok = (hh >= 0 && hh < NH && ww >= 0 && ww < NW);
            const float* src = ok
                ? &prev_embed[((size_t)(b * NC + c0 + cc)) * NP + hh * NW + ww]
                : prev_embed;
            cpa16z(aP + (uint32_t)(sel * 3840 + cc * 480 + rr * 40 + j4) * 4, src, ok ? 16 : 0);
        }
        #pragma unroll
        for (int r = 0; r < 2; r++) {                // cur: 256 float4
            int i = tid + r * 128;
            int cc = i >> 5, p4 = (i & 31) * 4;
            int hh = h0 + (p4 >> 5), ww = w0 + (p4 & 31);
            cpa16(aC + (uint32_t)(sel * 1024 + cc * 128 + p4) * 4,
                  &cur_embed[((size_t)(b * NC + c0 + cc)) * NP + hh * NW + ww]);
        }
    };

    float acc[9][9];
    #pragma unroll
    for (int dy = 0; dy < 9; dy++)
        #pragma unroll
        for (int dx = 0; dx < 9; dx++) acc[dy][dx] = 0.f;

    fill(0);
    CP_COMMIT();
    for (int ch = 0; ch < 32; ch++) {
        CP_WAIT0();
        __syncthreads();
        if (ch + 1 < 32) { fill(ch + 1); CP_COMMIT(); }
        int sel = ch & 1;
        const float* C = &curS[sel * 1024];
        const float* P = &prevT[sel * 3840];
        for (int cc = 0; cc < 8; cc++) {
            float cv = C[cc * 128 + tid];
            const float* Pr = &P[cc * 480 + ty * 40 + tx];
            #pragma unroll
            for (int dy = 0; dy < 9; dy++)
                #pragma unroll
                for (int dx = 0; dx < 9; dx++)
                    acc[dy][dx] += cv * Pr[dy * 40 + dx];
        }
    }

    // seg halo tile (zero-filled OOB), then branch-free epilogue
    __syncthreads();
    #pragma unroll
    for (int r = 0; r < 2; r++) {
        int i = tid + r * 128;
        if (i < 240) {
            int cls = i / 120, rem = i % 120, rr = rem / 10, j4 = (rem % 10) * 4;
            int hh = h0 - 4 + rr, ww = w0 - 4 + j4;
            bool ok = (hh >= 0 && hh < NH && ww >= 0 && ww < NW);
            const float* src = ok
                ? &prev_seg[((size_t)(b * 2 + cls)) * NP + hh * NW + ww]
                : prev_seg;
            cpa16z(aS + (uint32_t)(cls * 480 + rr * 40 + j4) * 4, src, ok ? 16 : 0);
        }
    }
    CP_COMMIT();
    CP_WAIT0();
    __syncthreads();

    float m0 = -1e30f, m1 = -1e30f;
    const float* S0 = &segS[ty * 40 + tx];
    const float* S1 = &segS[480 + ty * 40 + tx];
    #pragma unroll
    for (int dy = 0; dy < 9; dy++)
        #pragma unroll
        for (int dx = 0; dx < 9; dx++) {
            float raw = acc[dy][dx] * (1.f / 256.f);
            m0 = fmaxf(m0, raw * S0[dy * 40 + dx]);
            m1 = fmaxf(m1, raw * S1[dy * 40 + dx]);
        }
    int p = (h0 + ty) * NW + w0 + tx;
    g_aux[((size_t)b * 8 + 4) * NP + p] = m0;
    g_aux[((size_t)b * 8 + 5) * NP + p] = m1;
}

// =========================================================================
// Kernel 4: conv1 264->128, 3x3, SAME, ReLU.  FFMA2 8px x 8oc per thread,
// cp.async double-buffered 4-channel chunks (66), ONE sync per chunk.
// Block: 128 px (4 rows x 32 cols) x 128 oc, 256 threads.
// =========================================================================
__global__ __launch_bounds__(256, 2) void conv1_kernel(const float* __restrict__ cur_decode,
                                                       const float* __restrict__ b1) {
    __shared__ __align__(16) float inT[2][816];     // 4ic x 6 x 34
    __shared__ __align__(16) float wT[2][36 * 132]; // [(ic*9+k)][oc] pad 132
    int b = blockIdx.z;
    int row0 = blockIdx.y * 4;
    int col0 = blockIdx.x * 32;
    int tid = threadIdx.x;
    int to = tid & 15;                    // oc group
    int tp = tid >> 4;                    // 16 pixel-threads
    int prow = tp >> 2;                   // 0..3
    int pcol0 = (tp & 3) * 8;             // 0,8,16,24
    uint32_t aI = smem_u32(&inT[0][0]);
    uint32_t aW = smem_u32(&wT[0][0]);

    auto fill = [&](int ci) {
        int sel = ci & 1, ic0 = ci * 4;
        for (int i = tid; i < 816; i += 256) {
            int ic = i / 204, rem = i % 204, r = rem / 34, c2 = rem % 34;
            int hh = row0 + r - 1, ww = col0 + c2 - 1;
            bool ok = (hh >= 0 && hh < NH && ww >= 0 && ww < NW);
            int icg = ic0 + ic;
            const float* src;
            if (!ok) src = cur_decode;
            else if (icg < 256) src = &cur_decode[((size_t)(b * 256 + icg)) * NP + hh * NW + ww];
            else src = &g_aux[((size_t)b * 8 + icg - 256) * NP + hh * NW + ww];
            cpa4z(aI + (uint32_t)(sel * 816 + i) * 4, src, ok ? 4 : 0);
        }
        for (int j = tid; j < 1152; j += 256) {       // 36x128 weights as float4
            int r = j >> 5, q4 = (j & 31) * 4;
            cpa16(aW + (uint32_t)(sel * 4752 + r * 132 + q4) * 4,
                  &g_w1t[(size_t)(ic0 * 9 + r) * 128 + q4]);
        }
    };

    unsigned long long acc2[8][4];
    #pragma unroll
    for (int px = 0; px < 8; px++)
        #pragma unroll
        for (int q = 0; q < 4; q++) acc2[px][q] = 0ull;

    fill(0);
    CP_COMMIT();
    for (int ci = 0; ci < 66; ci++) {
        CP_WAIT0();
        __syncthreads();
        if (ci + 1 < 66) { fill(ci + 1); CP_COMMIT(); }
        int sel = ci & 1;
        const float* I = inT[sel];
        const float* W = wT[sel];
        #pragma unroll
        for (int ic = 0; ic < 4; ic++) {
            #pragma unroll
            for (int ky = 0; ky < 3; ky++) {
                const float* wrow = &I[ic * 204 + (prow + ky) * 34 + pcol0];
                unsigned long long ap[10];
                #pragma unroll
                for (int j = 0; j < 10; j++) { float v = wrow[j]; ap[j] = pk2(v, v); }
                #pragma unroll
                for (int kx = 0; kx < 3; kx++) {
                    const float* wr = &W[(ic * 9 + ky * 3 + kx) * 132];
                    ulonglong2 wa = *(const ulonglong2*)&wr[to * 4];
                    ulonglong2 wb = *(const ulonglong2*)&wr[64 + to * 4];
                    unsigned long long wp0 = wa.x, wp1 = wa.y, wp2 = wb.x, wp3 = wb.y;
                    #pragma unroll
                    for (int px = 0; px < 8; px++) {
                        unsigned long long a = ap[px + kx];
                        acc2[px][0] = f2fma(a, wp0, acc2[px][0]);
                        acc2[px][1] = f2fma(a, wp1, acc2[px][1]);
                        acc2[px][2] = f2fma(a, wp2, acc2[px][2]);
                        acc2[px][3] = f2fma(a, wp3, acc2[px][3]);
                    }
                }
            }
        }
    }
    // epilogue: bias + relu + store
    int obase[4] = {to * 4, to * 4 + 2, 64 + to * 4, 64 + to * 4 + 2};
    #pragma unroll
    for (int q = 0; q < 4; q++) {
        int oc0 = obase[q];
        float ba = b1[oc0], bb = b1[oc0 + 1];
        #pragma unroll
        for (int px = 0; px < 8; px++) {
            float lo, hi;
            upk2(acc2[px][q], lo, hi);
            int p = (row0 + prow) * NW + col0 + pcol0 + px;
            g_h[((size_t)(b * 128 + oc0)) * NP + p] = fmaxf(lo + ba, 0.f);
            g_h[((size_t)(b * 128 + oc0 + 1)) * NP + p] = fmaxf(hi + bb, 0.f);
        }
    }
}

// =========================================================================
// Kernel 5: conv2 128->2, 3x3, SAME (small).
// =========================================================================
__global__ void conv2_kernel(const float* __restrict__ W2,
                             const float* __restrict__ b2,
                             float* __restrict__ out) {
    __shared__ float w2s[2 * 128 * 9];
    __shared__ float hT[8][10][34];
    int b = blockIdx.z;
    int row0 = blockIdx.y * 8;
    int col0 = blockIdx.x * 32;
    int tid = threadIdx.x;
    int ty = tid >> 5, tx = tid & 31;
    for (int i = tid; i < 2304; i += 256) w2s[i] = W2[i];
    float a0 = b2[0], a1 = b2[1];

    for (int ic0 = 0; ic0 < 128; ic0 += 8) {
        __syncthreads();
        for (int i = tid; i < 8 * 340; i += 256) {
            int ic = i / 340, rem = i % 340, r = rem / 34, c2 = rem % 34;
            int hh = row0 + r - 1, ww = col0 + c2 - 1;
            float v = 0.f;
            if (hh >= 0 && hh < NH && ww >= 0 && ww < NW)
                v = g_h[((size_t)(b * 128 + ic0 + ic)) * NP + hh * NW + ww];
            hT[ic][r][c2] = v;
        }
        __syncthreads();
        #pragma unroll
        for (int ic = 0; ic < 8; ic++) {
            #pragma unroll
            for (int ky = 0; ky < 3; ky++)
                #pragma unroll
                for (int kx = 0; kx < 3; kx++) {
                    float v = hT[ic][ty + ky][tx + kx];
                    int wi = (ic0 + ic) * 9 + ky * 3 + kx;
                    a0 += v * w2s[wi];
                    a1 += v * w2s[1152 + wi];
                }
        }
    }
    int p = (row0 + ty) * NW + col0 + tx;
    out[((size_t)(b * 2 + 0)) * NP + p] = a0;
    out[((size_t)(b * 2 + 1)) * NP + p] = a1;
}

// =========================================================================
extern "C" void kernel_launch(void* const* d_in, const int* in_sizes, int n_in,
                              void* d_out, int out_size) {
    const float* cur_embed  = (const float*)d_in[0];
    const float* cur_decode = (const float*)d_in[1];
    const float* init_embed = (const float*)d_in[2];
    const float* init_seg   = (const float*)d_in[3];
    const float* prev_embed = (const float*)d_in[4];
    const float* prev_seg   = (const float*)d_in[5];
    const float* W1 = (const float*)d_in[6];
    const float* b1 = (const float*)d_in[7];
    const float* W2 = (const float*)d_in[8];
    const float* b2 = (const float*)d_in[9];
    float* out = (float*)d_out;

    int npool = NB * NC * NK + NB * 2 * NK + 2 * NB * 2 * NP + 2376 * 128;
    pool_kernel<<<(npool + 255) / 256, 256>>>(init_embed, init_seg, prev_seg, W1);
    gmap_kernel<<<dim3(NP / 128, NB), 256>>>(cur_embed);
    corr_kernel<<<dim3(NW / 32, NH / 4, NB), 128>>>(cur_embed, prev_embed, prev_seg);
    conv1_kernel<<<dim3(NW / 32, NH / 4, NB), 256>>>(cur_decode, b1);
    conv2_kernel<<<dim3(NW / 32, NH / 8, NB), 256>>>(W2, b2, out);
}

// round 11
// speedup vs baseline: 2.4221x; 1.1805x over previous
#include <cuda_runtime.h>
#include <cstdint>

// Problem constants
constexpr int NB = 8;          // batch
constexpr int NC = 256;        // embed channels
constexpr int NH = 96;
constexpr int NW = 96;
constexpr int NP = NH * NW;    // 9216 pixels
constexpr int NK = 576;        // pooled 24*24
constexpr int NHP = 24;

// ---------------- device scratch (no allocations allowed) ----------------
__device__ float g_fi[NB * NC * NK];     // pooled init_embed  (b,c,k)
__device__ float g_si[NB * 2 * NK];      // pooled init_seg    (b,2,k)
__device__ float g_aux[NB * 8 * NP];     // ch 256..263: [gmap0,gmap1,iseg0,iseg1,lmap0,lmap1,pseg0,pseg1]
__device__ float g_h[NB * 128 * NP];     // conv1 activations
__device__ float g_w1t[2376 * 128];      // W1 transposed: [(ic*9+k)][oc]

// ---------------- packed f32x2 helpers (Blackwell FFMA2) ----------------
__device__ __forceinline__ unsigned long long pk2(float lo, float hi) {
    unsigned long long r;
    asm("mov.b64 %0,{%1,%2};" : "=l"(r) : "f"(lo), "f"(hi));
    return r;
}
__device__ __forceinline__ unsigned long long f2fma(unsigned long long a,
                                                    unsigned long long b,
                                                    unsigned long long c) {
    unsigned long long d;
    asm("fma.rn.f32x2 %0,%1,%2,%3;" : "=l"(d) : "l"(a), "l"(b), "l"(c));
    return d;
}
__device__ __forceinline__ void upk2(unsigned long long p, float& lo, float& hi) {
    asm("mov.b64 {%0,%1},%2;" : "=f"(lo), "=f"(hi) : "l"(p));
}

// ---------------- cp.async helpers ----------------
__device__ __forceinline__ uint32_t smem_u32(const void* p) {
    uint32_t a;
    asm("{ .reg .u64 t; cvta.to.shared.u64 t, %1; cvt.u32.u64 %0, t; }"
        : "=r"(a) : "l"(p));
    return a;
}
__device__ __forceinline__ void cpa16(uint32_t dst, const void* src) {
    asm volatile("cp.async.ca.shared.global [%0],[%1],16;" :: "r"(dst), "l"(src));
}
// 16-byte copy with zero-fill when sz==0 (src must still be a valid address)
__device__ __forceinline__ void cpa16z(uint32_t dst, const void* src, int sz) {
    asm volatile("cp.async.ca.shared.global [%0],[%1],16,%2;"
                 :: "r"(dst), "l"(src), "r"(sz));
}
// 4-byte copy with zero-fill when sz==0
__device__ __forceinline__ void cpa4z(uint32_t dst, const void* src, int sz) {
    asm volatile("cp.async.ca.shared.global [%0],[%1],4,%2;"
                 :: "r"(dst), "l"(src), "r"(sz));
}
#define CP_COMMIT() asm volatile("cp.async.commit_group;" ::: "memory")
#define CP_WAIT0()  asm volatile("cp.async.wait_group 0;" ::: "memory")

// =========================================================================
// Kernel 1: avg_pool4 (init_embed -> g_fi, init_seg -> g_si), seg copies
// into aux channels, and one-time W1 transpose into g_w1t.
// =========================================================================
__global__ void pool_kernel(const float* __restrict__ init_embed,
                            const float* __restrict__ init_seg,
                            const float* __restrict__ prev_seg,
                            const float* __restrict__ W1) {
    int idx = blockIdx.x * blockDim.x + threadIdx.x;
    const int NFI = NB * NC * NK;
    const int NSI = NB * 2 * NK;
    const int NCP = NB * 2 * NP;
    const int NWT = 2376 * 128;
    if (idx < NFI) {
        int b = idx / (NC * NK);
        int r = idx % (NC * NK);
        int c = r / NK;
        int k = r % NK;
        int hp = k / NHP, wp = k % NHP;
        const float* src = init_embed + ((size_t)(b * NC + c) * NH + hp * 4) * NW + wp * 4;
        float s = 0.f;
        #pragma unroll
        for (int i = 0; i < 4; i++)
            #pragma unroll
            for (int j = 0; j < 4; j++) s += src[i * NW + j];
        g_fi[idx] = s * (1.f / 16.f);
    } else if (idx < NFI + NSI) {
        int t = idx - NFI;
        int b = t / (2 * NK);
        int r = t % (2 * NK);
        int c = r / NK;
        int k = r % NK;
        int hp = k / NHP, wp = k % NHP;
        const float* src = init_seg + ((size_t)(b * 2 + c) * NH + hp * 4) * NW + wp * 4;
        float s = 0.f;
        #pragma unroll
        for (int i = 0; i < 4; i++)
            #pragma unroll
            for (int j = 0; j < 4; j++) s += src[i * NW + j];
        g_si[t] = s * (1.f / 16.f);
    } else if (idx < NFI + NSI + 2 * NCP) {
        int t = idx - NFI - NSI;
        int which = t / NCP;            // 0: init_seg -> aux[2,3]; 1: prev_seg -> aux[6,7]
        int r = t % NCP;
        int b = r / (2 * NP);
        int rem = r % (2 * NP);
        int c = rem / NP;
        int p = rem % NP;
        float v = which ? prev_seg[r] : init_seg[r];
        g_aux[((size_t)b * 8 + (which ? 6 : 2) + c) * NP + p] = v;
    } else if (idx < NFI + NSI + 2 * NCP + NWT) {
        int t = idx - NFI - NSI - 2 * NCP;   // t = r*128 + oc  (coalesced writes)
        int r = t >> 7;
        int oc = t & 127;
        g_w1t[t] = W1[(size_t)oc * 2376 + r];
    }
}

// =========================================================================
// Kernel 2: global map.  sim[k,p] = sum_c fi[c,k]*cur[c,p];
// gmap[cls,p] = max_k sim[k,p]*si[cls,k].
// Block 128px x 96k, 256 thr (32 px-thr x 8 k-thr), thread 4px x 12k FFMA2.
// 16-channel chunks, 2-stage cp.async pipeline.  it = kt*16+ct, 6x16=96 iters.
// Non-FFMA2 overhead per cc: 4 LDS.128 + 4 pk2 vs 24 FFMA2 -> fma-pipe bound.
// =========================================================================
__global__ __launch_bounds__(256) void gmap_kernel(const float* __restrict__ cur_embed) {
    __shared__ __align__(16) float sA[2 * 2048];   // [sel][cc*128+px], 16 cc
    __shared__ __align__(16) float sB[2 * 1536];   // [sel][cc*96+k]
    __shared__ __align__(16) float sSi[1152];      // si[2][576] for this batch
    __shared__ float red[8 * 132];
    int tid = threadIdx.x;
    int ktid = tid & 7;        // 8 k-threads, each 12 k
    int ptid = tid >> 3;       // 32 px-threads, each 4 px
    int b = blockIdx.y;
    int p0 = blockIdx.x * 128;

    uint32_t aA = smem_u32(&sA[0]);
    uint32_t aB = smem_u32(&sB[0]);
    uint32_t aSi = smem_u32(&sSi[0]);

    auto fillchunk = [&](int it) {
        int kt = it >> 4, ct = it & 15, sel = it & 1;
        int c0 = ct * 16;
        uint32_t basA = aA + (uint32_t)(sel * 2048) * 4;
        uint32_t basB = aB + (uint32_t)(sel * 1536) * 4;
        #pragma unroll
        for (int r = 0; r < 2; r++) {            // A: 512 float4
            int i = tid + r * 256;
            int cc = i >> 5, x4 = (i & 31) * 4;
            cpa16(basA + (uint32_t)(cc * 128 + x4) * 4,
                  &cur_embed[((size_t)(b * NC + c0 + cc)) * NP + p0 + x4]);
        }
        for (int j = tid; j < 384; j += 256) {   // B: 384 float4
            int cc = j / 24, x4 = (j % 24) * 4;
            cpa16(basB + (uint32_t)(cc * 96 + x4) * 4,
                  &g_fi[((size_t)(b * NC + c0 + cc)) * NK + kt * 96 + x4]);
        }
    };

    // prologue: si + chunk0 in one group
    for (int j = tid; j < 288; j += 256)
        cpa16(aSi + (uint32_t)j * 16, &g_si[b * 2 * NK + j * 4]);
    fillchunk(0);
    CP_COMMIT();

    float m0[4], m1[4];
    #pragma unroll
    for (int i = 0; i < 4; i++) { m0[i] = -1e30f; m1[i] = -1e30f; }
    unsigned long long acc2[4][6];

    for (int it = 0; it < 96; it++) {
        int kt = it >> 4, ct = it & 15, sel = it & 1;
        CP_WAIT0();
        __syncthreads();                       // fill(it) visible; compute(it-1) done
        if (it + 1 < 96) { fillchunk(it + 1); CP_COMMIT(); }
        if (ct == 0) {
            #pragma unroll
            for (int px = 0; px < 4; px++)
                #pragma unroll
                for (int qq = 0; qq < 6; qq++) acc2[px][qq] = 0ull;
        }
        const float* A = &sA[sel * 2048];
        const float* B = &sB[sel * 1536];
        #pragma unroll
        for (int cc = 0; cc < 16; cc++) {
            float4 Av = *(const float4*)&A[cc * 128 + ptid * 4];
            ulonglong2 B0 = *(const ulonglong2*)&B[cc * 96 + ktid * 12];
            ulonglong2 B1 = *(const ulonglong2*)&B[cc * 96 + ktid * 12 + 4];
            ulonglong2 B2 = *(const ulonglong2*)&B[cc * 96 + ktid * 12 + 8];
            unsigned long long ap[4];
            ap[0] = pk2(Av.x, Av.x); ap[1] = pk2(Av.y, Av.y);
            ap[2] = pk2(Av.z, Av.z); ap[3] = pk2(Av.w, Av.w);
            unsigned long long bq[6] = {B0.x, B0.y, B1.x, B1.y, B2.x, B2.y};
            #pragma unroll
            for (int px = 0; px < 4; px++) {
                #pragma unroll
                for (int qq = 0; qq < 6; qq++)
                    acc2[px][qq] = f2fma(ap[px], bq[qq], acc2[px][qq]);
            }
        }
        if (ct == 15) {   // fold this k-tile into the running max
            #pragma unroll
            for (int qq = 0; qq < 6; qq++) {
                int kk = kt * 96 + ktid * 12 + 2 * qq;
                float s0a = sSi[kk], s0b = sSi[kk + 1];
                float s1a = sSi[NK + kk], s1b = sSi[NK + kk + 1];
                #pragma unroll
                for (int px = 0; px < 4; px++) {
                    float lo, hi;
                    upk2(acc2[px][qq], lo, hi);
                    m0[px] = fmaxf(m0[px], fmaxf(lo * s0a, hi * s0b));
                    m1[px] = fmaxf(m1[px], fmaxf(lo * s1a, hi * s1b));
                }
            }
        }
    }

    // reduce max across the 8 k-threads per pixel, per class
    __syncthreads();
    #pragma unroll
    for (int i = 0; i < 4; i++) red[ktid * 132 + ptid * 4 + i] = m0[i];
    __syncthreads();
    for (int s = 4; s > 0; s >>= 1) {
        if (ktid < s)
            #pragma unroll
            for (int i = 0; i < 4; i++) {
                int px = ptid * 4 + i;
                red[ktid * 132 + px] = fmaxf(red[ktid * 132 + px], red[(ktid + s) * 132 + px]);
            }
        __syncthreads();
    }
    if (ktid == 0)
        #pragma unroll
        for (int i = 0; i < 4; i++)
            g_aux[((size_t)b * 8 + 0) * NP + p0 + ptid * 4 + i] = red[ptid * 4 + i];
    __syncthreads();
    #pragma unroll
    for (int i = 0; i < 4; i++) red[ktid * 132 + ptid * 4 + i] = m1[i];
    __syncthreads();
    for (int s = 4; s > 0; s >>= 1) {
        if (ktid < s)
            #pragma unroll
            for (int i = 0; i < 4; i++) {
                int px = ptid * 4 + i;
                red[ktid * 132 + px] = fmaxf(red[ktid * 132 + px], red[(ktid + s) * 132 + px]);
            }
        __syncthreads();
    }
    if (ktid == 0)
        #pragma unroll
        for (int i = 0; i < 4; i++)
            g_aux[((size_t)b * 8 + 1) * NP + p0 + ptid * 4 + i] = red[ptid * 4 + i];
}

// =========================================================================
// Kernel 3: local correlation, single 12-row halo, all-81 accumulators.
// raw(p,d) = sum_c cur[c,p]*prev[c,p+d]/C ; lmap = max_d raw*seg(p+d).
// OOB displacements: prev halo zero-filled -> raw=0; seg smem zero-filled
// -> contribution 0 (matches the reference's zero-pad + max).
// 128 threads = 4x32 pixel tile; 32 channel-chunks of 8, N=2 pipeline.
// =========================================================================
__global__ __launch_bounds__(128) void corr_kernel(const float* __restrict__ cur_embed,
                                                   const float* __restrict__ prev_embed,
                                                   const float* __restrict__ prev_seg) {
    __shared__ __align__(16) float prevT[2 * 3840];  // [sel][cc*480 + rr*40 + col]
    __shared__ __align__(16) float curS[2 * 1024];   // [sel][cc*128 + tid]
    __shared__ __align__(16) float segS[960];        // [cls*480 + rr*40 + col]
    int b = blockIdx.z;
    int h0 = blockIdx.y * 4;
    int w0 = blockIdx.x * 32;
    int tid = threadIdx.x;
    int ty = tid >> 5, tx = tid & 31;
    uint32_t aP = smem_u32(&prevT[0]);
    uint32_t aC = smem_u32(&curS[0]);
    uint32_t aS = smem_u32(&segS[0]);

    // halo rows h0-4 .. h0+7 (12), cols w0-4 .. w0+35 (40, 16B-aligned groups)
    auto fill = [&](int ch) {
        int sel = ch & 1, c0 = ch * 8;
        for (int i = tid; i < 960; i += 128) {       // prev: 960 float4
            int cc = i / 120, rem = i % 120, rr = rem / 10, j4 = (rem % 10) * 4;
            int hh = h0 - 4 + rr, ww = w0 - 4 + j4;
            bool ok = (hh >= 0 && hh < NH && ww >= 0 && ww < NW);
            const float* src = ok
                ? &prev_embed[((size_t)(b * NC + c0 + cc)) * NP + hh * NW + ww]
                : prev_embed;
            cpa16z(aP + (uint32_t)(sel * 3840 + cc * 480 + rr * 40 + j4) * 4, src, ok ? 16 : 0);
        }
        #pragma unroll
        for (int r = 0; r < 2; r++) {                // cur: 256 float4
            int i = tid + r * 128;
            int cc = i >> 5, p4 = (i & 31) * 4;
            int hh = h0 + (p4 >> 5), ww = w0 + (p4 & 31);
            cpa16(aC + (uint32_t)(sel * 1024 + cc * 128 + p4) * 4,
                  &cur_embed[((size_t)(b * NC + c0 + cc)) * NP + hh * NW + ww]);
        }
    };

    float acc[9][9];
    #pragma unroll
    for (int dy = 0; dy < 9; dy++)
        #pragma unroll
        for (int dx = 0; dx < 9; dx++) acc[dy][dx] = 0.f;

    fill(0);
    CP_COMMIT();
    for (int ch = 0; ch < 32; ch++) {
        CP_WAIT0();
        __syncthreads();
        if (ch + 1 < 32) { fill(ch + 1); CP_COMMIT(); }
        int sel = ch & 1;
        const float* C = &curS[sel * 1024];
        const float* P = &prevT[sel * 3840];
        for (int cc = 0; cc < 8; cc++) {
            float cv = C[cc * 128 + tid];
            const float* Pr = &P[cc * 480 + ty * 40 + tx];
            #pragma unroll
            for (int dy = 0; dy < 9; dy++)
                #pragma unroll
                for (int dx = 0; dx < 9; dx++)
                    acc[dy][dx] += cv * Pr[dy * 40 + dx];
        }
    }

    // seg halo tile (zero-filled OOB), then branch-free epilogue
    __syncthreads();
    #pragma unroll
    for (int r = 0; r < 2; r++) {
        int i = tid + r * 128;
        if (i < 240) {
            int cls = i / 120, rem = i % 120, rr = rem / 10, j4 = (rem % 10) * 4;
            int hh = h0 - 4 + rr, ww = w0 - 4 + j4;
            bool ok = (hh >= 0 && hh < NH && ww >= 0 && ww < NW);
            const float* src = ok
                ? &prev_seg[((size_t)(b * 2 + cls)) * NP + hh * NW + ww]
                : prev_seg;
            cpa16z(aS + (uint32_t)(cls * 480 + rr * 40 + j4) * 4, src, ok ? 16 : 0);
        }
    }
    CP_COMMIT();
    CP_WAIT0();
    __syncthreads();

    float m0 = -1e30f, m1 = -1e30f;
    const float* S0 = &segS[ty * 40 + tx];
    const float* S1 = &segS[480 + ty * 40 + tx];
    #pragma unroll
    for (int dy = 0; dy < 9; dy++)
        #pragma unroll
        for (int dx = 0; dx < 9; dx++) {
            float raw = acc[dy][dx] * (1.f / 256.f);
            m0 = fmaxf(m0, raw * S0[dy * 40 + dx]);
            m1 = fmaxf(m1, raw * S1[dy * 40 + dx]);
        }
    int p = (h0 + ty) * NW + w0 + tx;
    g_aux[((size_t)b * 8 + 4) * NP + p] = m0;
    g_aux[((size_t)b * 8 + 5) * NP + p] = m1;
}

// =========================================================================
// Kernel 4: conv1 264->128, 3x3, SAME, ReLU.  FFMA2 8px x 8oc per thread,
// cp.async double-buffered 4-channel chunks (66), ONE sync per chunk.
// Halo stride padded to 36 so wrow loads vectorize (2 LDS.128 + 1 LDS.64).
// Block: 128 px (4 rows x 32 cols) x 128 oc, 256 threads.
// =========================================================================
__global__ __launch_bounds__(256, 2) void conv1_kernel(const float* __restrict__ cur_decode,
                                                       const float* __restrict__ b1) {
    __shared__ __align__(16) float inT[2][864];     // 4ic x 6 x 36 (cols 34,35 zero)
    __shared__ __align__(16) float wT[2][36 * 132]; // [(ic*9+k)][oc] pad 132
    int b = blockIdx.z;
    int row0 = blockIdx.y * 4;
    int col0 = blockIdx.x * 32;
    int tid = threadIdx.x;
    int to = tid & 15;                    // oc group
    int tp = tid >> 4;                    // 16 pixel-threads
    int prow = tp >> 2;                   // 0..3
    int pcol0 = (tp & 3) * 8;             // 0,8,16,24
    uint32_t aI = smem_u32(&inT[0][0]);
    uint32_t aW = smem_u32(&wT[0][0]);

    auto fill = [&](int ci) {
        int sel = ci & 1, ic0 = ci * 4;
        for (int i = tid; i < 864; i += 256) {
            int ic = i / 216, rem = i % 216, r = rem / 36, c2 = rem % 36;
            int hh = row0 + r - 1, ww = col0 + c2 - 1;
            bool ok = (c2 < 34) && (hh >= 0 && hh < NH && ww >= 0 && ww < NW);
            int icg = ic0 + ic;
            const float* src;
            if (!ok) src = cur_decode;
            else if (icg < 256) src = &cur_decode[((size_t)(b * 256 + icg)) * NP + hh * NW + ww];
            else src = &g_aux[((size_t)b * 8 + icg - 256) * NP + hh * NW + ww];
            cpa4z(aI + (uint32_t)(sel * 864 + i) * 4, src, ok ? 4 : 0);
        }
        for (int j = tid; j < 1152; j += 256) {       // 36x128 weights as float4
            int r = j >> 5, q4 = (j & 31) * 4;
            cpa16(aW + (uint32_t)(sel * 4752 + r * 132 + q4) * 4,
                  &g_w1t[(size_t)(ic0 * 9 + r) * 128 + q4]);
        }
    };

    unsigned long long acc2[8][4];
    #pragma unroll
    for (int px = 0; px < 8; px++)
        #pragma unroll
        for (int q = 0; q < 4; q++) acc2[px][q] = 0ull;

    fill(0);
    CP_COMMIT();
    for (int ci = 0; ci < 66; ci++) {
        CP_WAIT0();
        __syncthreads();
        if (ci + 1 < 66) { fill(ci + 1); CP_COMMIT(); }
        int sel = ci & 1;
        const float* I = inT[sel];
        const float* W = wT[sel];
        #pragma unroll
        for (int ic = 0; ic < 4; ic++) {
            #pragma unroll
            for (int ky = 0; ky < 3; ky++) {
                const float* wrow = &I[ic * 216 + (prow + ky) * 36 + pcol0];
                float4 wv0 = *(const float4*)wrow;
                float4 wv1 = *(const float4*)(wrow + 4);
                float2 wv2 = *(const float2*)(wrow + 8);
                unsigned long long ap[10];
                ap[0] = pk2(wv0.x, wv0.x); ap[1] = pk2(wv0.y, wv0.y);
                ap[2] = pk2(wv0.z, wv0.z); ap[3] = pk2(wv0.w, wv0.w);
                ap[4] = pk2(wv1.x, wv1.x); ap[5] = pk2(wv1.y, wv1.y);
                ap[6] = pk2(wv1.z, wv1.z); ap[7] = pk2(wv1.w, wv1.w);
                ap[8] = pk2(wv2.x, wv2.x); ap[9] = pk2(wv2.y, wv2.y);
                #pragma unroll
                for (int kx = 0; kx < 3; kx++) {
                    const float* wr = &W[(ic * 9 + ky * 3 + kx) * 132];
                    ulonglong2 wa = *(const ulonglong2*)&wr[to * 4];
                    ulonglong2 wb = *(const ulonglong2*)&wr[64 + to * 4];
                    unsigned long long wp0 = wa.x, wp1 = wa.y, wp2 = wb.x, wp3 = wb.y;
                    #pragma unroll
                    for (int px = 0; px < 8; px++) {
                        unsigned long long a = ap[px + kx];
                        acc2[px][0] = f2fma(a, wp0, acc2[px][0]);
                        acc2[px][1] = f2fma(a, wp1, acc2[px][1]);
                        acc2[px][2] = f2fma(a, wp2, acc2[px][2]);
                        acc2[px][3] = f2fma(a, wp3, acc2[px][3]);
                    }
                }
            }
        }
    }
    // epilogue: bias + relu + store
    int obase[4] = {to * 4, to * 4 + 2, 64 + to * 4, 64 + to * 4 + 2};
    #pragma unroll
    for (int q = 0; q < 4; q++) {
        int oc0 = obase[q];
        float ba = b1[oc0], bb = b1[oc0 + 1];
        #pragma unroll
        for (int px = 0; px < 8; px++) {
            float lo, hi;
            upk2(acc2[px][q], lo, hi);
            int p = (row0 + prow) * NW + col0 + pcol0 + px;
            g_h[((size_t)(b * 128 + oc0)) * NP + p] = fmaxf(lo + ba, 0.f);
            g_h[((size_t)(b * 128 + oc0 + 1)) * NP + p] = fmaxf(hi + bb, 0.f);
        }
    }
}

// =========================================================================
// Kernel 5: conv2 128->2, 3x3, SAME (small).
// =========================================================================
__global__ void conv2_kernel(const float* __restrict__ W2,
                             const float* __restrict__ b2,
                             float* __restrict__ out) {
    __shared__ float w2s[2 * 128 * 9];
    __shared__ float hT[8][10][34];
    int b = blockIdx.z;
    int row0 = blockIdx.y * 8;
    int col0 = blockIdx.x * 32;
    int tid = threadIdx.x;
    int ty = tid >> 5, tx = tid & 31;
    for (int i = tid; i < 2304; i += 256) w2s[i] = W2[i];
    float a0 = b2[0], a1 = b2[1];

    for (int ic0 = 0; ic0 < 128; ic0 += 8) {
        __syncthreads();
        for (int i = tid; i < 8 * 340; i += 256) {
            int ic = i / 340, rem = i % 340, r = rem / 34, c2 = rem % 34;
            int hh = row0 + r - 1, ww = col0 + c2 - 1;
            float v = 0.f;
            if (hh >= 0 && hh < NH && ww >= 0 && ww < NW)
                v = g_h[((size_t)(b * 128 + ic0 + ic)) * NP + hh * NW + ww];
            hT[ic][r][c2] = v;
        }
        __syncthreads();
        #pragma unroll
        for (int ic = 0; ic < 8; ic++) {
            #pragma unroll
            for (int ky = 0; ky < 3; ky++)
                #pragma unroll
                for (int kx = 0; kx < 3; kx++) {
                    float v = hT[ic][ty + ky][tx + kx];
                    int wi = (ic0 + ic) * 9 + ky * 3 + kx;
                    a0 += v * w2s[wi];
                    a1 += v * w2s[1152 + wi];
                }
        }
    }
    int p = (row0 + ty) * NW + col0 + tx;
    out[((size_t)(b * 2 + 0)) * NP + p] = a0;
    out[((size_t)(b * 2 + 1)) * NP + p] = a1;
}

// =========================================================================
extern "C" void kernel_launch(void* const* d_in, const int* in_sizes, int n_in,
                              void* d_out, int out_size) {
    const float* cur_embed  = (const float*)d_in[0];
    const float* cur_decode = (const float*)d_in[1];
    const float* init_embed = (const float*)d_in[2];
    const float* init_seg   = (const float*)d_in[3];
    const float* prev_embed = (const float*)d_in[4];
    const float* prev_seg   = (const float*)d_in[5];
    const float* W1 = (const float*)d_in[6];
    const float* b1 = (const float*)d_in[7];
    const float* W2 = (const float*)d_in[8];
    const float* b2 = (const float*)d_in[9];
    float* out = (float*)d_out;

    int npool = NB * NC * NK + NB * 2 * NK + 2 * NB * 2 * NP + 2376 * 128;
    pool_kernel<<<(npool + 255) / 256, 256>>>(init_embed, init_seg, prev_seg, W1);
    gmap_kernel<<<dim3(NP / 128, NB), 256>>>(cur_embed);
    corr_kernel<<<dim3(NW / 32, NH / 4, NB), 128>>>(cur_embed, prev_embed, prev_seg);
    conv1_kernel<<<dim3(NW / 32, NH / 4, NB), 256>>>(cur_decode, b1);
    conv2_kernel<<<dim3(NW / 32, NH / 8, NB), 256>>>(W2, b2, out);
}